// round 6
// baseline (speedup 1.0000x reference)
#include <cuda_runtime.h>
#include <cuda_bf16.h>
#include <math.h>

#define BB 512
#define NN 2048
#define QDIM 64
#define FP16_HUGE 32768.0f

// ---------------- scratch ----------------
__device__ float g_qsum[BB * 4 * 64];    // partial masked sums (4 quarters per batch)
__device__ float g_msum[BB * 4];
__device__ float g_wmp[BB * 8 * 8 * 64]; // partial wm per chunk
__device__ float g_esp[BB * 8 * 8];      // partial esum per chunk
__device__ float g_wa[BB * 64];

// ---------------- K1: partial masked sum of q_data (4 CTAs per batch) ----------------
__global__ void k_qavg(const float* __restrict__ q_data, const float* __restrict__ q_mask) {
    int b   = blockIdx.x >> 2;
    int qtr = blockIdx.x & 3;
    int tid = threadIdx.x;          // 256
    int rg  = tid >> 4;             // 0..15 row group
    int cq  = (tid & 15) << 2;      // channel quad
    int n0  = qtr * 512;
    const float* qb = q_data + (size_t)b * NN * QDIM;
    const float* mb = q_mask + (size_t)b * NN;
    float4 acc = make_float4(0.f, 0.f, 0.f, 0.f);
    float ms = 0.f;
#pragma unroll 4
    for (int n = n0 + rg; n < n0 + 512; n += 32) {
        float m0 = mb[n];
        float m1 = mb[n + 16];
        float4 a = *(const float4*)&qb[(size_t)n * QDIM + cq];
        float4 c = *(const float4*)&qb[(size_t)(n + 16) * QDIM + cq];
        acc.x = fmaf(m0, a.x, acc.x); acc.y = fmaf(m0, a.y, acc.y);
        acc.z = fmaf(m0, a.z, acc.z); acc.w = fmaf(m0, a.w, acc.w);
        acc.x = fmaf(m1, c.x, acc.x); acc.y = fmaf(m1, c.y, acc.y);
        acc.z = fmaf(m1, c.z, acc.z); acc.w = fmaf(m1, c.w, acc.w);
        ms += m0 + m1;
    }
    __shared__ float4 sa[16][16];
    __shared__ float  sm[16];
    sa[rg][tid & 15] = acc;
    if ((tid & 15) == 0) sm[rg] = ms;
    __syncthreads();
    if (tid < 16) {
        float4 t = make_float4(0.f, 0.f, 0.f, 0.f);
        float msum = 0.f;
#pragma unroll
        for (int r = 0; r < 16; r++) {
            float4 v = sa[r][tid];
            t.x += v.x; t.y += v.y; t.z += v.z; t.w += v.w;
            msum += sm[r];
        }
        float* dst = g_qsum + (b * 4 + qtr) * 64 + tid * 4;
        dst[0] = t.x; dst[1] = t.y; dst[2] = t.z; dst[3] = t.w;
        if (tid == 0) g_msum[b * 4 + qtr] = msum;
    }
}

// ---------------- K2: fused attention, 8 chunks per batch (2 tiles each) ----------------
#define MS_STR 68
__global__ void k_attn2(const float* __restrict__ m_data,
                        const float* __restrict__ q_mask,
                        const float* __restrict__ query_w,
                        const float* __restrict__ key_w) {
    __shared__ __align__(16) float ms[128 * MS_STR];
    __shared__ __align__(16) float es[8 * 132];
    __shared__ __align__(16) float qk_s[512];    // [a][h]
    __shared__ float qh_s[64];
    __shared__ float qa_s[64];
    __shared__ float msk[128];

    int b     = blockIdx.x >> 3;
    int chunk = blockIdx.x & 7;
    int tid   = threadIdx.x;   // 256

    if (tid < 64) {
        float msum = g_msum[b * 4] + g_msum[b * 4 + 1] + g_msum[b * 4 + 2] + g_msum[b * 4 + 3];
        const float* qp = g_qsum + b * 256 + tid;
        qa_s[tid] = (qp[0] + qp[64] + qp[128] + qp[192]) / (msum + 1e-10f);
    }
    __syncthreads();
    if (tid < 64) {
        float s = 0.f;
#pragma unroll 16
        for (int d = 0; d < 64; d++) s = fmaf(qa_s[d], query_w[d * 64 + tid], s);
        qh_s[tid] = s * 0.35355339059327373f;   // KD^-0.5
    }
    __syncthreads();
#pragma unroll
    for (int it = 0; it < 2; it++) {
        int i = tid + it * 256;
        int a = i >> 3, h = i & 7;
        float s = 0.f;
#pragma unroll
        for (int c = 0; c < 8; c++) s = fmaf(key_w[a * 8 + c], qh_s[h * 8 + c], s);
        qk_s[a * 8 + h] = s;
    }

    int nloc = tid >> 1;
    int hg   = tid & 1;
    int h    = tid >> 5;
    int a0   = (tid & 31) << 1;

    float wm0 = 0.f, wm1 = 0.f;
    float esr = 0.f;

    const float* mb = q_mask + (size_t)b * NN;

    for (int tile = chunk * 2; tile < chunk * 2 + 2; tile++) {
        __syncthreads();
        const float4* msrc = (const float4*)(m_data + ((size_t)b * NN + tile * 128) * 64);
#pragma unroll
        for (int it = 0; it < 8; it++) {
            int i = tid + it * 256;
            float4 v = msrc[i];
            int r = i >> 4, c = (i & 15) << 2;
            float* d = ms + r * MS_STR + c;
            d[0] = v.x; d[1] = v.y; d[2] = v.z; d[3] = v.w;
        }
        if (tid < 128) msk[tid] = mb[tile * 128 + tid];
        __syncthreads();
        // ---- e phase ----
        {
            float4 acc = make_float4(0.f, 0.f, 0.f, 0.f);
            const float* mrow = ms + nloc * MS_STR;
#pragma unroll
            for (int a = 0; a < 64; a += 4) {
                float4 mv = *(const float4*)&mrow[a];
                float4 k0 = *(const float4*)&qk_s[(a + 0) * 8 + hg * 4];
                float4 k1 = *(const float4*)&qk_s[(a + 1) * 8 + hg * 4];
                float4 k2 = *(const float4*)&qk_s[(a + 2) * 8 + hg * 4];
                float4 k3 = *(const float4*)&qk_s[(a + 3) * 8 + hg * 4];
                acc.x = fmaf(mv.x, k0.x, acc.x); acc.y = fmaf(mv.x, k0.y, acc.y);
                acc.z = fmaf(mv.x, k0.z, acc.z); acc.w = fmaf(mv.x, k0.w, acc.w);
                acc.x = fmaf(mv.y, k1.x, acc.x); acc.y = fmaf(mv.y, k1.y, acc.y);
                acc.z = fmaf(mv.y, k1.z, acc.z); acc.w = fmaf(mv.y, k1.w, acc.w);
                acc.x = fmaf(mv.z, k2.x, acc.x); acc.y = fmaf(mv.z, k2.y, acc.y);
                acc.z = fmaf(mv.z, k2.z, acc.z); acc.w = fmaf(mv.z, k2.w, acc.w);
                acc.x = fmaf(mv.w, k3.x, acc.x); acc.y = fmaf(mv.w, k3.y, acc.y);
                acc.z = fmaf(mv.w, k3.z, acc.z); acc.w = fmaf(mv.w, k3.w, acc.w);
            }
            float mbias = FP16_HUGE * (msk[nloc] - 1.0f);
            es[(hg * 4 + 0) * 132 + nloc] = __expf(acc.x + mbias);
            es[(hg * 4 + 1) * 132 + nloc] = __expf(acc.y + mbias);
            es[(hg * 4 + 2) * 132 + nloc] = __expf(acc.z + mbias);
            es[(hg * 4 + 3) * 132 + nloc] = __expf(acc.w + mbias);
        }
        __syncthreads();
        // ---- wm phase ----
#pragma unroll 8
        for (int n4 = 0; n4 < 128; n4 += 4) {
            float4 e4 = *(const float4*)&es[h * 132 + n4];
            float2 m0 = *(const float2*)&ms[(n4 + 0) * MS_STR + a0];
            float2 m1 = *(const float2*)&ms[(n4 + 1) * MS_STR + a0];
            float2 m2 = *(const float2*)&ms[(n4 + 2) * MS_STR + a0];
            float2 m3 = *(const float2*)&ms[(n4 + 3) * MS_STR + a0];
            wm0 = fmaf(e4.x, m0.x, wm0); wm1 = fmaf(e4.x, m0.y, wm1);
            wm0 = fmaf(e4.y, m1.x, wm0); wm1 = fmaf(e4.y, m1.y, wm1);
            wm0 = fmaf(e4.z, m2.x, wm0); wm1 = fmaf(e4.z, m2.y, wm1);
            wm0 = fmaf(e4.w, m3.x, wm0); wm1 = fmaf(e4.w, m3.y, wm1);
            esr += e4.x + e4.y + e4.z + e4.w;
        }
    }
    float* wmp = g_wmp + ((size_t)(b * 8 + chunk) * 8 + h) * 64;
    wmp[a0] = wm0;
    wmp[a0 + 1] = wm1;
    if ((tid & 31) == 0) g_esp[(b * 8 + chunk) * 8 + h] = esr;
}

// ---------------- K2b: finalize wa = (sum_chunks wm) @ value_w / esum ----------------
__global__ void k_wafin(const float* __restrict__ value_w) {
    __shared__ float wm_s[8 * 65];
    __shared__ float es_s[8];
    int b = blockIdx.x;
    int tid = threadIdx.x;   // 64
    for (int i = tid; i < 512; i += 64) {
        const float* p = g_wmp + (size_t)b * 8 * 512 + i;
        float s = 0.f;
#pragma unroll
        for (int c = 0; c < 8; c++) s += p[c * 512];
        wm_s[(i >> 6) * 65 + (i & 63)] = s;
    }
    if (tid < 8) {
        const float* p = g_esp + b * 64 + tid;
        float s = 0.f;
#pragma unroll
        for (int c = 0; c < 8; c++) s += p[c * 8];
        es_s[tid] = s;
    }
    __syncthreads();
    int h = tid >> 3, v = tid & 7;
    float s = 0.f;
#pragma unroll 16
    for (int a = 0; a < 64; a++) s = fmaf(wm_s[h * 65 + a], value_w[a * 8 + v], s);
    g_wa[b * 64 + tid] = s / es_s[h];
}

// ---------------- K3: gate + output, tf32 mma, 32 rows/warp (B-fragment reuse) ----------------
__device__ __forceinline__ unsigned f2tf(float x) {
    unsigned r; asm("cvt.rna.tf32.f32 %0, %1;" : "=r"(r) : "f"(x)); return r;
}
__device__ __forceinline__ void ldm_x4(unsigned& r0, unsigned& r1, unsigned& r2, unsigned& r3,
                                       unsigned addr) {
    asm volatile("ldmatrix.sync.aligned.m8n8.x4.shared.b16 {%0,%1,%2,%3}, [%4];"
                 : "=r"(r0), "=r"(r1), "=r"(r2), "=r"(r3) : "r"(addr));
}
__device__ __forceinline__ void ldm_x2(unsigned& r0, unsigned& r1, unsigned addr) {
    asm volatile("ldmatrix.sync.aligned.m8n8.x2.shared.b16 {%0,%1}, [%2];"
                 : "=r"(r0), "=r"(r1) : "r"(addr));
}
#define MMA_TF32(C, A0, A1, A2, A3, B0, B1)                                     \
    asm volatile(                                                               \
        "mma.sync.aligned.m16n8k8.row.col.f32.tf32.tf32.f32 "                   \
        "{%0,%1,%2,%3}, {%4,%5,%6,%7}, {%8,%9}, {%0,%1,%2,%3};\n"               \
        : "+f"((C)[0]), "+f"((C)[1]), "+f"((C)[2]), "+f"((C)[3])                \
        : "r"(A0), "r"(A1), "r"(A2), "r"(A3), "r"(B0), "r"(B1))

#define QS_STRIDE 68
#define WB_STRIDE 68
#define SMEM_FLOATS (128 * QS_STRIDE + 64 * WB_STRIDE + 192)

__global__ __launch_bounds__(128, 4)
void k_main(const float* __restrict__ q_data,
            const float* __restrict__ gating_w,
            const float* __restrict__ gating_b,
            const float* __restrict__ output_w,
            const float* __restrict__ output_b,
            float* __restrict__ out) {
    extern __shared__ float sh[];
    float* qs   = sh;                         // 128 x 68 : q tile, then gate tile
    float* wb   = sh + 128 * QS_STRIDE;       // 64 x 68  : transposed [n][k] weights
    float* gb_s = wb + 64 * WB_STRIDE;
    float* ob_s = gb_s + 64;
    float* wa_s = ob_s + 64;

    int b    = blockIdx.y;
    int rt   = blockIdx.x;
    int tid  = threadIdx.x;    // 128 (4 warps, 32 rows each)
    int warp = tid >> 5;
    int lane = tid & 31;
    int g    = lane >> 2;
    int t    = lane & 3;

    if (tid < 64) {
        gb_s[tid] = gating_b[tid];
        ob_s[tid] = output_b[tid];
        wa_s[tid] = g_wa[b * 64 + tid];
    }
    const float4* qsrc = (const float4*)(q_data + ((size_t)b * NN + (size_t)rt * 128) * QDIM);
#pragma unroll
    for (int it = 0; it < 16; it++) {
        int i = tid + it * 128;
        float4 v = qsrc[i];
        int r = i >> 4, c = (i & 15) << 2;
        float* d = qs + r * QS_STRIDE + c;
        d[0] = __uint_as_float(f2tf(v.x)); d[1] = __uint_as_float(f2tf(v.y));
        d[2] = __uint_as_float(f2tf(v.z)); d[3] = __uint_as_float(f2tf(v.w));
    }
#pragma unroll
    for (int it = 0; it < 8; it++) {
        int i = tid + it * 128;
        float4 v = ((const float4*)gating_w)[i];
        int k = i >> 4, nq = (i & 15) << 2;
        wb[(nq + 0) * WB_STRIDE + k] = __uint_as_float(f2tf(v.x));
        wb[(nq + 1) * WB_STRIDE + k] = __uint_as_float(f2tf(v.y));
        wb[(nq + 2) * WB_STRIDE + k] = __uint_as_float(f2tf(v.z));
        wb[(nq + 3) * WB_STRIDE + k] = __uint_as_float(f2tf(v.w));
    }
    __syncthreads();

    unsigned qs_base = (unsigned)__cvta_generic_to_shared(qs);
    unsigned wb_base = (unsigned)__cvta_generic_to_shared(wb);
    int mi = lane >> 3;
    // A fragment base for mt tile: rows warp*32 + mt*16
    unsigned a_row0 = warp * 32 + (lane & 7) + (mi & 1) * 8;
    unsigned a_off0 = qs_base + (a_row0 * QS_STRIDE + (mi >> 1) * 4) * 4;
    unsigned a_off1 = a_off0 + 16 * QS_STRIDE * 4;
    int lb = lane & 15;
    unsigned b_term = wb_base + ((lb & 7) * WB_STRIDE + (lb >> 3) * 4) * 4;

    float c_[2][8][4];
#pragma unroll
    for (int mt = 0; mt < 2; mt++)
#pragma unroll
        for (int nt = 0; nt < 8; nt++)
#pragma unroll
            for (int e = 0; e < 4; e++) c_[mt][nt][e] = 0.f;

    // ---- mma1: S = Q @ Gw ----
#pragma unroll
    for (int k8 = 0; k8 < 8; k8++) {
        unsigned a0[2], a1[2], a2[2], a3[2];
        ldm_x4(a0[0], a1[0], a2[0], a3[0], a_off0 + k8 * 32);
        ldm_x4(a0[1], a1[1], a2[1], a3[1], a_off1 + k8 * 32);
#pragma unroll
        for (int nt = 0; nt < 8; nt++) {
            unsigned b0, b1;
            ldm_x2(b0, b1, b_term + (unsigned)(nt * 8 * WB_STRIDE * 4 + k8 * 32));
            MMA_TF32(c_[0][nt], a0[0], a1[0], a2[0], a3[0], b0, b1);
            MMA_TF32(c_[1][nt], a0[1], a1[1], a2[1], a3[1], b0, b1);
        }
    }

    // ---- sigmoid gate -> qs (tf32) ----
#pragma unroll
    for (int mt = 0; mt < 2; mt++) {
        int r0 = warp * 32 + mt * 16;
#pragma unroll
        for (int nt = 0; nt < 8; nt++) {
            int col = nt * 8 + 2 * t;
            float bb0 = gb_s[col], bb1 = gb_s[col + 1];
            float g0 = 1.f / (1.f + __expf(-(c_[mt][nt][0] + bb0)));
            float g1 = 1.f / (1.f + __expf(-(c_[mt][nt][1] + bb1)));
            float g2 = 1.f / (1.f + __expf(-(c_[mt][nt][2] + bb0)));
            float g3 = 1.f / (1.f + __expf(-(c_[mt][nt][3] + bb1)));
            qs[(r0 + g)     * QS_STRIDE + col]     = __uint_as_float(f2tf(g0));
            qs[(r0 + g)     * QS_STRIDE + col + 1] = __uint_as_float(f2tf(g1));
            qs[(r0 + 8 + g) * QS_STRIDE + col]     = __uint_as_float(f2tf(g2));
            qs[(r0 + 8 + g) * QS_STRIDE + col + 1] = __uint_as_float(f2tf(g3));
        }
    }
    __syncthreads();   // all warps done reading wb (Gw)
    // ---- W2 = wa (.) output_w -> wb transposed ----
#pragma unroll
    for (int it = 0; it < 8; it++) {
        int i = tid + it * 128;
        float4 v = ((const float4*)output_w)[i];
        int k = i >> 4, nq = (i & 15) << 2;
        float w = wa_s[k];
        wb[(nq + 0) * WB_STRIDE + k] = __uint_as_float(f2tf(w * v.x));
        wb[(nq + 1) * WB_STRIDE + k] = __uint_as_float(f2tf(w * v.y));
        wb[(nq + 2) * WB_STRIDE + k] = __uint_as_float(f2tf(w * v.z));
        wb[(nq + 3) * WB_STRIDE + k] = __uint_as_float(f2tf(w * v.w));
    }
    __syncthreads();

#pragma unroll
    for (int mt = 0; mt < 2; mt++)
#pragma unroll
        for (int nt = 0; nt < 8; nt++)
#pragma unroll
            for (int e = 0; e < 4; e++) c_[mt][nt][e] = 0.f;

    // ---- mma2: out = gate @ W2 ----
#pragma unroll
    for (int k8 = 0; k8 < 8; k8++) {
        unsigned a0[2], a1[2], a2[2], a3[2];
        ldm_x4(a0[0], a1[0], a2[0], a3[0], a_off0 + k8 * 32);
        ldm_x4(a0[1], a1[1], a2[1], a3[1], a_off1 + k8 * 32);
#pragma unroll
        for (int nt = 0; nt < 8; nt++) {
            unsigned b0, b1;
            ldm_x2(b0, b1, b_term + (unsigned)(nt * 8 * WB_STRIDE * 4 + k8 * 32));
            MMA_TF32(c_[0][nt], a0[0], a1[0], a2[0], a3[0], b0, b1);
            MMA_TF32(c_[1][nt], a0[1], a1[1], a2[1], a3[1], b0, b1);
        }
    }

    // ---- epilogue ----
    float* outp = out + ((size_t)b * NN + (size_t)rt * 128) * 64;
#pragma unroll
    for (int mt = 0; mt < 2; mt++) {
        int r0 = warp * 32 + mt * 16 + g;
#pragma unroll
        for (int nt = 0; nt < 8; nt++) {
            int col = nt * 8 + 2 * t;
            float o0 = ob_s[col], o1 = ob_s[col + 1];
            *(float2*)&outp[(size_t)r0 * 64 + col] =
                make_float2(c_[mt][nt][0] + o0, c_[mt][nt][1] + o1);
            *(float2*)&outp[(size_t)(r0 + 8) * 64 + col] =
                make_float2(c_[mt][nt][2] + o0, c_[mt][nt][3] + o1);
        }
    }
}

// ---------------- launch ----------------
extern "C" void kernel_launch(void* const* d_in, const int* in_sizes, int n_in,
                              void* d_out, int out_size) {
    const float* q_data   = (const float*)d_in[0];
    const float* m_data   = (const float*)d_in[1];
    const float* q_mask   = (const float*)d_in[2];
    const float* query_w  = (const float*)d_in[4];
    const float* key_w    = (const float*)d_in[5];
    const float* value_w  = (const float*)d_in[6];
    const float* gating_w = (const float*)d_in[7];
    const float* gating_b = (const float*)d_in[8];
    const float* output_w = (const float*)d_in[9];
    const float* output_b = (const float*)d_in[10];
    float* out = (float*)d_out;

    k_qavg<<<BB * 4, 256>>>(q_data, q_mask);
    k_attn2<<<BB * 8, 256>>>(m_data, q_mask, query_w, key_w);
    k_wafin<<<BB, 64>>>(value_w);

    int smem = SMEM_FLOATS * 4;
    cudaFuncSetAttribute(k_main, cudaFuncAttributeMaxDynamicSharedMemorySize, smem);
    k_main<<<dim3(NN / 128, BB), 128, smem>>>(q_data, gating_w, gating_b,
                                              output_w, output_b, out);
}

// round 7
// speedup vs baseline: 1.0338x; 1.0338x over previous
#include <cuda_runtime.h>
#include <cuda_bf16.h>
#include <math.h>

#define BB 512
#define NN 2048
#define QDIM 64
#define FP16_HUGE 32768.0f

// ---------------- scratch ----------------
__device__ float g_qsum[BB * 4 * 64];
__device__ float g_msum[BB * 4];
__device__ float g_wmp[BB * 8 * 8 * 64];
__device__ float g_esp[BB * 8 * 8];
__device__ float g_wa[BB * 64];

// ---------------- K1: partial masked sum of q_data (4 CTAs per batch) ----------------
__global__ void k_qavg(const float* __restrict__ q_data, const float* __restrict__ q_mask) {
    int b   = blockIdx.x >> 2;
    int qtr = blockIdx.x & 3;
    int tid = threadIdx.x;          // 256
    int rg  = tid >> 4;
    int cq  = (tid & 15) << 2;
    int n0  = qtr * 512;
    const float* qb = q_data + (size_t)b * NN * QDIM;
    const float* mb = q_mask + (size_t)b * NN;
    float4 acc = make_float4(0.f, 0.f, 0.f, 0.f);
    float ms = 0.f;
#pragma unroll 4
    for (int n = n0 + rg; n < n0 + 512; n += 32) {
        float m0 = mb[n];
        float m1 = mb[n + 16];
        float4 a = *(const float4*)&qb[(size_t)n * QDIM + cq];
        float4 c = *(const float4*)&qb[(size_t)(n + 16) * QDIM + cq];
        acc.x = fmaf(m0, a.x, acc.x); acc.y = fmaf(m0, a.y, acc.y);
        acc.z = fmaf(m0, a.z, acc.z); acc.w = fmaf(m0, a.w, acc.w);
        acc.x = fmaf(m1, c.x, acc.x); acc.y = fmaf(m1, c.y, acc.y);
        acc.z = fmaf(m1, c.z, acc.z); acc.w = fmaf(m1, c.w, acc.w);
        ms += m0 + m1;
    }
    __shared__ float4 sa[16][16];
    __shared__ float  sm[16];
    sa[rg][tid & 15] = acc;
    if ((tid & 15) == 0) sm[rg] = ms;
    __syncthreads();
    if (tid < 16) {
        float4 t = make_float4(0.f, 0.f, 0.f, 0.f);
        float msum = 0.f;
#pragma unroll
        for (int r = 0; r < 16; r++) {
            float4 v = sa[r][tid];
            t.x += v.x; t.y += v.y; t.z += v.z; t.w += v.w;
            msum += sm[r];
        }
        float* dst = g_qsum + (b * 4 + qtr) * 64 + tid * 4;
        dst[0] = t.x; dst[1] = t.y; dst[2] = t.z; dst[3] = t.w;
        if (tid == 0) g_msum[b * 4 + qtr] = msum;
    }
}

// ---------------- K2: fused attention, 8 chunks per batch (2 tiles each) ----------------
#define MS_STR 68
__global__ void k_attn2(const float* __restrict__ m_data,
                        const float* __restrict__ q_mask,
                        const float* __restrict__ query_w,
                        const float* __restrict__ key_w) {
    __shared__ __align__(16) float ms[128 * MS_STR];
    __shared__ __align__(16) float es[8 * 132];
    __shared__ __align__(16) float qk_s[512];
    __shared__ float qh_s[64];
    __shared__ float qa_s[64];
    __shared__ float msk[128];

    int b     = blockIdx.x >> 3;
    int chunk = blockIdx.x & 7;
    int tid   = threadIdx.x;   // 256

    if (tid < 64) {
        float msum = g_msum[b * 4] + g_msum[b * 4 + 1] + g_msum[b * 4 + 2] + g_msum[b * 4 + 3];
        const float* qp = g_qsum + b * 256 + tid;
        qa_s[tid] = (qp[0] + qp[64] + qp[128] + qp[192]) / (msum + 1e-10f);
    }
    __syncthreads();
    if (tid < 64) {
        float s = 0.f;
#pragma unroll 16
        for (int d = 0; d < 64; d++) s = fmaf(qa_s[d], query_w[d * 64 + tid], s);
        qh_s[tid] = s * 0.35355339059327373f;
    }
    __syncthreads();
#pragma unroll
    for (int it = 0; it < 2; it++) {
        int i = tid + it * 256;
        int a = i >> 3, h = i & 7;
        float s = 0.f;
#pragma unroll
        for (int c = 0; c < 8; c++) s = fmaf(key_w[a * 8 + c], qh_s[h * 8 + c], s);
        qk_s[a * 8 + h] = s;
    }

    int nloc = tid >> 1;
    int hg   = tid & 1;
    int h    = tid >> 5;
    int a0   = (tid & 31) << 1;

    float wm0 = 0.f, wm1 = 0.f;
    float esr = 0.f;

    const float* mb = q_mask + (size_t)b * NN;

    for (int tile = chunk * 2; tile < chunk * 2 + 2; tile++) {
        __syncthreads();
        const float4* msrc = (const float4*)(m_data + ((size_t)b * NN + tile * 128) * 64);
#pragma unroll
        for (int it = 0; it < 8; it++) {
            int i = tid + it * 256;
            float4 v = msrc[i];
            int r = i >> 4, c = (i & 15) << 2;
            float* d = ms + r * MS_STR + c;
            d[0] = v.x; d[1] = v.y; d[2] = v.z; d[3] = v.w;
        }
        if (tid < 128) msk[tid] = mb[tile * 128 + tid];
        __syncthreads();
        // ---- e phase ----
        {
            float4 acc = make_float4(0.f, 0.f, 0.f, 0.f);
            const float* mrow = ms + nloc * MS_STR;
#pragma unroll
            for (int a = 0; a < 64; a += 4) {
                float4 mv = *(const float4*)&mrow[a];
                float4 k0 = *(const float4*)&qk_s[(a + 0) * 8 + hg * 4];
                float4 k1 = *(const float4*)&qk_s[(a + 1) * 8 + hg * 4];
                float4 k2 = *(const float4*)&qk_s[(a + 2) * 8 + hg * 4];
                float4 k3 = *(const float4*)&qk_s[(a + 3) * 8 + hg * 4];
                acc.x = fmaf(mv.x, k0.x, acc.x); acc.y = fmaf(mv.x, k0.y, acc.y);
                acc.z = fmaf(mv.x, k0.z, acc.z); acc.w = fmaf(mv.x, k0.w, acc.w);
                acc.x = fmaf(mv.y, k1.x, acc.x); acc.y = fmaf(mv.y, k1.y, acc.y);
                acc.z = fmaf(mv.y, k1.z, acc.z); acc.w = fmaf(mv.y, k1.w, acc.w);
                acc.x = fmaf(mv.z, k2.x, acc.x); acc.y = fmaf(mv.z, k2.y, acc.y);
                acc.z = fmaf(mv.z, k2.z, acc.z); acc.w = fmaf(mv.z, k2.w, acc.w);
                acc.x = fmaf(mv.w, k3.x, acc.x); acc.y = fmaf(mv.w, k3.y, acc.y);
                acc.z = fmaf(mv.w, k3.z, acc.z); acc.w = fmaf(mv.w, k3.w, acc.w);
            }
            float mbias = FP16_HUGE * (msk[nloc] - 1.0f);
            es[(hg * 4 + 0) * 132 + nloc] = __expf(acc.x + mbias);
            es[(hg * 4 + 1) * 132 + nloc] = __expf(acc.y + mbias);
            es[(hg * 4 + 2) * 132 + nloc] = __expf(acc.z + mbias);
            es[(hg * 4 + 3) * 132 + nloc] = __expf(acc.w + mbias);
        }
        __syncthreads();
        // ---- wm phase ----
#pragma unroll 8
        for (int n4 = 0; n4 < 128; n4 += 4) {
            float4 e4 = *(const float4*)&es[h * 132 + n4];
            float2 m0 = *(const float2*)&ms[(n4 + 0) * MS_STR + a0];
            float2 m1 = *(const float2*)&ms[(n4 + 1) * MS_STR + a0];
            float2 m2 = *(const float2*)&ms[(n4 + 2) * MS_STR + a0];
            float2 m3 = *(const float2*)&ms[(n4 + 3) * MS_STR + a0];
            wm0 = fmaf(e4.x, m0.x, wm0); wm1 = fmaf(e4.x, m0.y, wm1);
            wm0 = fmaf(e4.y, m1.x, wm0); wm1 = fmaf(e4.y, m1.y, wm1);
            wm0 = fmaf(e4.z, m2.x, wm0); wm1 = fmaf(e4.z, m2.y, wm1);
            wm0 = fmaf(e4.w, m3.x, wm0); wm1 = fmaf(e4.w, m3.y, wm1);
            esr += e4.x + e4.y + e4.z + e4.w;
        }
    }
    float* wmp = g_wmp + ((size_t)(b * 8 + chunk) * 8 + h) * 64;
    wmp[a0] = wm0;
    wmp[a0 + 1] = wm1;
    if ((tid & 31) == 0) g_esp[(b * 8 + chunk) * 8 + h] = esr;
}

// ---------------- K2b: finalize wa ----------------
__global__ void k_wafin(const float* __restrict__ value_w) {
    __shared__ float wm_s[8 * 65];
    __shared__ float es_s[8];
    int b = blockIdx.x;
    int tid = threadIdx.x;   // 64
    for (int i = tid; i < 512; i += 64) {
        const float* p = g_wmp + (size_t)b * 8 * 512 + i;
        float s = 0.f;
#pragma unroll
        for (int c = 0; c < 8; c++) s += p[c * 512];
        wm_s[(i >> 6) * 65 + (i & 63)] = s;
    }
    if (tid < 8) {
        const float* p = g_esp + b * 64 + tid;
        float s = 0.f;
#pragma unroll
        for (int c = 0; c < 8; c++) s += p[c * 8];
        es_s[tid] = s;
    }
    __syncthreads();
    int h = tid >> 3, v = tid & 7;
    float s = 0.f;
#pragma unroll 16
    for (int a = 0; a < 64; a++) s = fmaf(wm_s[h * 65 + a], value_w[a * 8 + v], s);
    g_wa[b * 64 + tid] = s / es_s[h];
}

// ---------------- K3: gate + output; 8 warps, M x N split, x4 ldmatrix both operands --------
__device__ __forceinline__ unsigned f2tf(float x) {
    unsigned r; asm("cvt.rna.tf32.f32 %0, %1;" : "=r"(r) : "f"(x)); return r;
}
__device__ __forceinline__ void ldm_x4(unsigned& r0, unsigned& r1, unsigned& r2, unsigned& r3,
                                       unsigned addr) {
    asm volatile("ldmatrix.sync.aligned.m8n8.x4.shared.b16 {%0,%1,%2,%3}, [%4];"
                 : "=r"(r0), "=r"(r1), "=r"(r2), "=r"(r3) : "r"(addr));
}
#define MMA_TF32(C, A0, A1, A2, A3, B0, B1)                                     \
    asm volatile(                                                               \
        "mma.sync.aligned.m16n8k8.row.col.f32.tf32.tf32.f32 "                   \
        "{%0,%1,%2,%3}, {%4,%5,%6,%7}, {%8,%9}, {%0,%1,%2,%3};\n"               \
        : "+f"((C)[0]), "+f"((C)[1]), "+f"((C)[2]), "+f"((C)[3])                \
        : "r"(A0), "r"(A1), "r"(A2), "r"(A3), "r"(B0), "r"(B1))

#define QS_STRIDE 68
#define WB_STRIDE 68
#define SMEM_FLOATS (128 * QS_STRIDE + 64 * WB_STRIDE + 192)

__global__ __launch_bounds__(256, 4)
void k_main(const float* __restrict__ q_data,
            const float* __restrict__ gating_w,
            const float* __restrict__ gating_b,
            const float* __restrict__ output_w,
            const float* __restrict__ output_b,
            float* __restrict__ out) {
    extern __shared__ float sh[];
    float* qs   = sh;                         // 128 x 68 : q tile, then gate tile
    float* wb   = sh + 128 * QS_STRIDE;       // 64 x 68  : transposed [n][k] weights
    float* gb_s = wb + 64 * WB_STRIDE;
    float* ob_s = gb_s + 64;
    float* wa_s = ob_s + 64;

    int b    = blockIdx.y;
    int rt   = blockIdx.x;
    int tid  = threadIdx.x;    // 256: warp w -> rows (w&3)*32..+31, cols (w>>2)*32..+31
    int warp = tid >> 5;
    int lane = tid & 31;
    int g    = lane >> 2;
    int t    = lane & 3;
    int mw   = warp & 3;       // row-tile index
    int hN   = warp >> 2;      // N half

    if (tid < 64) {
        gb_s[tid] = gating_b[tid];
        ob_s[tid] = output_b[tid];
        wa_s[tid] = g_wa[b * 64 + tid];
    }
    const float4* qsrc = (const float4*)(q_data + ((size_t)b * NN + (size_t)rt * 128) * QDIM);
#pragma unroll
    for (int it = 0; it < 8; it++) {
        int i = tid + it * 256;
        float4 v = qsrc[i];
        int r = i >> 4, c = (i & 15) << 2;
        float* d = qs + r * QS_STRIDE + c;
        d[0] = __uint_as_float(f2tf(v.x)); d[1] = __uint_as_float(f2tf(v.y));
        d[2] = __uint_as_float(f2tf(v.z)); d[3] = __uint_as_float(f2tf(v.w));
    }
#pragma unroll
    for (int it = 0; it < 4; it++) {
        int i = tid + it * 256;
        float4 v = ((const float4*)gating_w)[i];
        int k = i >> 4, nq = (i & 15) << 2;
        wb[(nq + 0) * WB_STRIDE + k] = __uint_as_float(f2tf(v.x));
        wb[(nq + 1) * WB_STRIDE + k] = __uint_as_float(f2tf(v.y));
        wb[(nq + 2) * WB_STRIDE + k] = __uint_as_float(f2tf(v.z));
        wb[(nq + 3) * WB_STRIDE + k] = __uint_as_float(f2tf(v.w));
    }
    __syncthreads();

    unsigned qs_base = (unsigned)__cvta_generic_to_shared(qs);
    unsigned wb_base = (unsigned)__cvta_generic_to_shared(wb);
    // A fragment addresses: rows mw*32 (+16 for mt=1)
    int mi = lane >> 3;
    unsigned a_row0 = mw * 32 + (lane & 7) + (mi & 1) * 8;
    unsigned a_off0 = qs_base + (a_row0 * QS_STRIDE + (mi >> 1) * 4) * 4;
    unsigned a_off1 = a_off0 + 16 * QS_STRIDE * 4;
    // B x4 addresses: matrices {ntL, ntL(+4cols), ntL+1, ntL+1(+4cols)} for pair p
    //   lane -> mat = lane>>3, row = lane&7
    //   n = hN*32 + p*16 + (mat>>1)*8 + row ; col = (mat&1)*4  (+ k8*8 at use site)
    int bm   = lane >> 3;
    int brow = lane & 7;
    unsigned b_off0 = wb_base + ((unsigned)((hN * 32 + (bm >> 1) * 8 + brow) * WB_STRIDE
                                            + (bm & 1) * 4)) * 4;
    unsigned b_off1 = b_off0 + 16 * WB_STRIDE * 4;

    float c_[2][4][4];
#pragma unroll
    for (int mt = 0; mt < 2; mt++)
#pragma unroll
        for (int nt = 0; nt < 4; nt++)
#pragma unroll
            for (int e = 0; e < 4; e++) c_[mt][nt][e] = 0.f;

    // ---- mma1: S = Q @ Gw ----
#pragma unroll
    for (int k8 = 0; k8 < 8; k8++) {
        unsigned a0[2], a1[2], a2[2], a3[2];
        ldm_x4(a0[0], a1[0], a2[0], a3[0], a_off0 + k8 * 32);
        ldm_x4(a0[1], a1[1], a2[1], a3[1], a_off1 + k8 * 32);
        unsigned p0b0, p0b1, p0c0, p0c1, p1b0, p1b1, p1c0, p1c1;
        ldm_x4(p0b0, p0b1, p0c0, p0c1, b_off0 + k8 * 32);   // nt0 (b0,b1), nt1 (b0,b1)
        ldm_x4(p1b0, p1b1, p1c0, p1c1, b_off1 + k8 * 32);   // nt2, nt3
        MMA_TF32(c_[0][0], a0[0], a1[0], a2[0], a3[0], p0b0, p0b1);
        MMA_TF32(c_[1][0], a0[1], a1[1], a2[1], a3[1], p0b0, p0b1);
        MMA_TF32(c_[0][1], a0[0], a1[0], a2[0], a3[0], p0c0, p0c1);
        MMA_TF32(c_[1][1], a0[1], a1[1], a2[1], a3[1], p0c0, p0c1);
        MMA_TF32(c_[0][2], a0[0], a1[0], a2[0], a3[0], p1b0, p1b1);
        MMA_TF32(c_[1][2], a0[1], a1[1], a2[1], a3[1], p1b0, p1b1);
        MMA_TF32(c_[0][3], a0[0], a1[0], a2[0], a3[0], p1c0, p1c1);
        MMA_TF32(c_[1][3], a0[1], a1[1], a2[1], a3[1], p1c0, p1c1);
    }

    // ---- sigmoid gate -> qs (tf32), rows mw*32.., cols hN*32.. ----
#pragma unroll
    for (int mt = 0; mt < 2; mt++) {
        int r0 = mw * 32 + mt * 16;
#pragma unroll
        for (int nt = 0; nt < 4; nt++) {
            int col = hN * 32 + nt * 8 + 2 * t;
            float bb0 = gb_s[col], bb1 = gb_s[col + 1];
            float g0 = 1.f / (1.f + __expf(-(c_[mt][nt][0] + bb0)));
            float g1 = 1.f / (1.f + __expf(-(c_[mt][nt][1] + bb1)));
            float g2 = 1.f / (1.f + __expf(-(c_[mt][nt][2] + bb0)));
            float g3 = 1.f / (1.f + __expf(-(c_[mt][nt][3] + bb1)));
            qs[(r0 + g)     * QS_STRIDE + col]     = __uint_as_float(f2tf(g0));
            qs[(r0 + g)     * QS_STRIDE + col + 1] = __uint_as_float(f2tf(g1));
            qs[(r0 + 8 + g) * QS_STRIDE + col]     = __uint_as_float(f2tf(g2));
            qs[(r0 + 8 + g) * QS_STRIDE + col + 1] = __uint_as_float(f2tf(g3));
        }
    }
    __syncthreads();   // all warps done reading wb (Gw), gate fully written
    // ---- W2 = wa (.) output_w -> wb transposed ----
#pragma unroll
    for (int it = 0; it < 4; it++) {
        int i = tid + it * 256;
        float4 v = ((const float4*)output_w)[i];
        int k = i >> 4, nq = (i & 15) << 2;
        float w = wa_s[k];
        wb[(nq + 0) * WB_STRIDE + k] = __uint_as_float(f2tf(w * v.x));
        wb[(nq + 1) * WB_STRIDE + k] = __uint_as_float(f2tf(w * v.y));
        wb[(nq + 2) * WB_STRIDE + k] = __uint_as_float(f2tf(w * v.z));
        wb[(nq + 3) * WB_STRIDE + k] = __uint_as_float(f2tf(w * v.w));
    }
    __syncthreads();

#pragma unroll
    for (int mt = 0; mt < 2; mt++)
#pragma unroll
        for (int nt = 0; nt < 4; nt++)
#pragma unroll
            for (int e = 0; e < 4; e++) c_[mt][nt][e] = 0.f;

    // ---- mma2: out = gate @ W2 ----
#pragma unroll
    for (int k8 = 0; k8 < 8; k8++) {
        unsigned a0[2], a1[2], a2[2], a3[2];
        ldm_x4(a0[0], a1[0], a2[0], a3[0], a_off0 + k8 * 32);
        ldm_x4(a0[1], a1[1], a2[1], a3[1], a_off1 + k8 * 32);
        unsigned p0b0, p0b1, p0c0, p0c1, p1b0, p1b1, p1c0, p1c1;
        ldm_x4(p0b0, p0b1, p0c0, p0c1, b_off0 + k8 * 32);
        ldm_x4(p1b0, p1b1, p1c0, p1c1, b_off1 + k8 * 32);
        MMA_TF32(c_[0][0], a0[0], a1[0], a2[0], a3[0], p0b0, p0b1);
        MMA_TF32(c_[1][0], a0[1], a1[1], a2[1], a3[1], p0b0, p0b1);
        MMA_TF32(c_[0][1], a0[0], a1[0], a2[0], a3[0], p0c0, p0c1);
        MMA_TF32(c_[1][1], a0[1], a1[1], a2[1], a3[1], p0c0, p0c1);
        MMA_TF32(c_[0][2], a0[0], a1[0], a2[0], a3[0], p1b0, p1b1);
        MMA_TF32(c_[1][2], a0[1], a1[1], a2[1], a3[1], p1b0, p1b1);
        MMA_TF32(c_[0][3], a0[0], a1[0], a2[0], a3[0], p1c0, p1c1);
        MMA_TF32(c_[1][3], a0[1], a1[1], a2[1], a3[1], p1c0, p1c1);
    }

    // ---- epilogue: rows mw*32.., cols hN*32.. ----
    float* outp = out + ((size_t)b * NN + (size_t)rt * 128) * 64;
#pragma unroll
    for (int mt = 0; mt < 2; mt++) {
        int r0 = mw * 32 + mt * 16 + g;
#pragma unroll
        for (int nt = 0; nt < 4; nt++) {
            int col = hN * 32 + nt * 8 + 2 * t;
            float o0 = ob_s[col], o1 = ob_s[col + 1];
            *(float2*)&outp[(size_t)r0 * 64 + col] =
                make_float2(c_[mt][nt][0] + o0, c_[mt][nt][1] + o1);
            *(float2*)&outp[(size_t)(r0 + 8) * 64 + col] =
                make_float2(c_[mt][nt][2] + o0, c_[mt][nt][3] + o1);
        }
    }
}

// ---------------- launch ----------------
extern "C" void kernel_launch(void* const* d_in, const int* in_sizes, int n_in,
                              void* d_out, int out_size) {
    const float* q_data   = (const float*)d_in[0];
    const float* m_data   = (const float*)d_in[1];
    const float* q_mask   = (const float*)d_in[2];
    const float* query_w  = (const float*)d_in[4];
    const float* key_w    = (const float*)d_in[5];
    const float* value_w  = (const float*)d_in[6];
    const float* gating_w = (const float*)d_in[7];
    const float* gating_b = (const float*)d_in[8];
    const float* output_w = (const float*)d_in[9];
    const float* output_b = (const float*)d_in[10];
    float* out = (float*)d_out;

    k_qavg<<<BB * 4, 256>>>(q_data, q_mask);
    k_attn2<<<BB * 8, 256>>>(m_data, q_mask, query_w, key_w);
    k_wafin<<<BB, 64>>>(value_w);

    int smem = SMEM_FLOATS * 4;
    cudaFuncSetAttribute(k_main, cudaFuncAttributeMaxDynamicSharedMemorySize, smem);
    k_main<<<dim3(NN / 128, BB), 256, smem>>>(q_data, gating_w, gating_b,
                                              output_w, output_b, out);
}

// round 8
// speedup vs baseline: 1.1345x; 1.0974x over previous
#include <cuda_runtime.h>
#include <cuda_bf16.h>
#include <math.h>

#define BB 512
#define NN 2048
#define QDIM 64
#define FP16_HUGE 32768.0f

// ---------------- scratch ----------------
__device__ float g_qsum[BB * 4 * 64];
__device__ float g_msum[BB * 4];
__device__ float g_wmp[BB * 8 * 8 * 64];
__device__ float g_esp[BB * 8 * 8];
__device__ float g_wa[BB * 64];

// ---------------- K1: partial masked sum of q_data (4 CTAs per batch) ----------------
__global__ void k_qavg(const float* __restrict__ q_data, const float* __restrict__ q_mask) {
    int b   = blockIdx.x >> 2;
    int qtr = blockIdx.x & 3;
    int tid = threadIdx.x;          // 256
    int rg  = tid >> 4;
    int cq  = (tid & 15) << 2;
    int n0  = qtr * 512;
    const float* qb = q_data + (size_t)b * NN * QDIM;
    const float* mb = q_mask + (size_t)b * NN;
    float4 acc = make_float4(0.f, 0.f, 0.f, 0.f);
    float ms = 0.f;
#pragma unroll 4
    for (int n = n0 + rg; n < n0 + 512; n += 32) {
        float m0 = mb[n];
        float m1 = mb[n + 16];
        float4 a = *(const float4*)&qb[(size_t)n * QDIM + cq];
        float4 c = *(const float4*)&qb[(size_t)(n + 16) * QDIM + cq];
        acc.x = fmaf(m0, a.x, acc.x); acc.y = fmaf(m0, a.y, acc.y);
        acc.z = fmaf(m0, a.z, acc.z); acc.w = fmaf(m0, a.w, acc.w);
        acc.x = fmaf(m1, c.x, acc.x); acc.y = fmaf(m1, c.y, acc.y);
        acc.z = fmaf(m1, c.z, acc.z); acc.w = fmaf(m1, c.w, acc.w);
        ms += m0 + m1;
    }
    __shared__ float4 sa[16][16];
    __shared__ float  sm[16];
    sa[rg][tid & 15] = acc;
    if ((tid & 15) == 0) sm[rg] = ms;
    __syncthreads();
    if (tid < 16) {
        float4 t = make_float4(0.f, 0.f, 0.f, 0.f);
        float msum = 0.f;
#pragma unroll
        for (int r = 0; r < 16; r++) {
            float4 v = sa[r][tid];
            t.x += v.x; t.y += v.y; t.z += v.z; t.w += v.w;
            msum += sm[r];
        }
        float* dst = g_qsum + (b * 4 + qtr) * 64 + tid * 4;
        dst[0] = t.x; dst[1] = t.y; dst[2] = t.z; dst[3] = t.w;
        if (tid == 0) g_msum[b * 4 + qtr] = msum;
    }
}

// ---------------- K2: fused attention, 8 chunks per batch (2 tiles each) ----------------
#define MS_STR 68
__global__ void k_attn2(const float* __restrict__ m_data,
                        const float* __restrict__ q_mask,
                        const float* __restrict__ query_w,
                        const float* __restrict__ key_w) {
    __shared__ __align__(16) float ms[128 * MS_STR];
    __shared__ __align__(16) float es[8 * 132];
    __shared__ __align__(16) float qk_s[512];
    __shared__ float qh_s[64];
    __shared__ float qa_s[64];
    __shared__ float msk[128];

    int b     = blockIdx.x >> 3;
    int chunk = blockIdx.x & 7;
    int tid   = threadIdx.x;   // 256

    if (tid < 64) {
        float msum = g_msum[b * 4] + g_msum[b * 4 + 1] + g_msum[b * 4 + 2] + g_msum[b * 4 + 3];
        const float* qp = g_qsum + b * 256 + tid;
        qa_s[tid] = (qp[0] + qp[64] + qp[128] + qp[192]) / (msum + 1e-10f);
    }
    __syncthreads();
    if (tid < 64) {
        float s = 0.f;
#pragma unroll 16
        for (int d = 0; d < 64; d++) s = fmaf(qa_s[d], query_w[d * 64 + tid], s);
        qh_s[tid] = s * 0.35355339059327373f;
    }
    __syncthreads();
#pragma unroll
    for (int it = 0; it < 2; it++) {
        int i = tid + it * 256;
        int a = i >> 3, h = i & 7;
        float s = 0.f;
#pragma unroll
        for (int c = 0; c < 8; c++) s = fmaf(key_w[a * 8 + c], qh_s[h * 8 + c], s);
        qk_s[a * 8 + h] = s;
    }

    int nloc = tid >> 1;
    int hg   = tid & 1;
    int h    = tid >> 5;             // warp = head
    int half = (tid >> 4) & 1;       // token half for wm phase
    int a0   = (tid & 15) << 2;      // 4 channels per lane

    float4 wm = make_float4(0.f, 0.f, 0.f, 0.f);
    float esr = 0.f;

    const float* mb = q_mask + (size_t)b * NN;

    for (int tile = chunk * 2; tile < chunk * 2 + 2; tile++) {
        __syncthreads();
        const float4* msrc = (const float4*)(m_data + ((size_t)b * NN + tile * 128) * 64);
#pragma unroll
        for (int it = 0; it < 8; it++) {
            int i = tid + it * 256;
            float4 v = msrc[i];
            int r = i >> 4, c = (i & 15) << 2;
            float* d = ms + r * MS_STR + c;
            d[0] = v.x; d[1] = v.y; d[2] = v.z; d[3] = v.w;
        }
        if (tid < 128) msk[tid] = mb[tile * 128 + tid];
        __syncthreads();
        // ---- e phase ----
        {
            float4 acc = make_float4(0.f, 0.f, 0.f, 0.f);
            const float* mrow = ms + nloc * MS_STR;
#pragma unroll
            for (int a = 0; a < 64; a += 4) {
                float4 mv = *(const float4*)&mrow[a];
                float4 k0 = *(const float4*)&qk_s[(a + 0) * 8 + hg * 4];
                float4 k1 = *(const float4*)&qk_s[(a + 1) * 8 + hg * 4];
                float4 k2 = *(const float4*)&qk_s[(a + 2) * 8 + hg * 4];
                float4 k3 = *(const float4*)&qk_s[(a + 3) * 8 + hg * 4];
                acc.x = fmaf(mv.x, k0.x, acc.x); acc.y = fmaf(mv.x, k0.y, acc.y);
                acc.z = fmaf(mv.x, k0.z, acc.z); acc.w = fmaf(mv.x, k0.w, acc.w);
                acc.x = fmaf(mv.y, k1.x, acc.x); acc.y = fmaf(mv.y, k1.y, acc.y);
                acc.z = fmaf(mv.y, k1.z, acc.z); acc.w = fmaf(mv.y, k1.w, acc.w);
                acc.x = fmaf(mv.z, k2.x, acc.x); acc.y = fmaf(mv.z, k2.y, acc.y);
                acc.z = fmaf(mv.z, k2.z, acc.z); acc.w = fmaf(mv.z, k2.w, acc.w);
                acc.x = fmaf(mv.w, k3.x, acc.x); acc.y = fmaf(mv.w, k3.y, acc.y);
                acc.z = fmaf(mv.w, k3.z, acc.z); acc.w = fmaf(mv.w, k3.w, acc.w);
            }
            float mbias = FP16_HUGE * (msk[nloc] - 1.0f);
            es[(hg * 4 + 0) * 132 + nloc] = __expf(acc.x + mbias);
            es[(hg * 4 + 1) * 132 + nloc] = __expf(acc.y + mbias);
            es[(hg * 4 + 2) * 132 + nloc] = __expf(acc.z + mbias);
            es[(hg * 4 + 3) * 132 + nloc] = __expf(acc.w + mbias);
        }
        __syncthreads();
        // ---- wm phase: warp h, lanes split tokens in halves, float4 channels ----
#pragma unroll 4
        for (int n4 = 0; n4 < 64; n4 += 4) {
            int n = half * 64 + n4;
            float4 e4 = *(const float4*)&es[h * 132 + n];
            float4 m0 = *(const float4*)&ms[(n + 0) * MS_STR + a0];
            float4 m1 = *(const float4*)&ms[(n + 1) * MS_STR + a0];
            float4 m2 = *(const float4*)&ms[(n + 2) * MS_STR + a0];
            float4 m3 = *(const float4*)&ms[(n + 3) * MS_STR + a0];
            wm.x = fmaf(e4.x, m0.x, wm.x); wm.y = fmaf(e4.x, m0.y, wm.y);
            wm.z = fmaf(e4.x, m0.z, wm.z); wm.w = fmaf(e4.x, m0.w, wm.w);
            wm.x = fmaf(e4.y, m1.x, wm.x); wm.y = fmaf(e4.y, m1.y, wm.y);
            wm.z = fmaf(e4.y, m1.z, wm.z); wm.w = fmaf(e4.y, m1.w, wm.w);
            wm.x = fmaf(e4.z, m2.x, wm.x); wm.y = fmaf(e4.z, m2.y, wm.y);
            wm.z = fmaf(e4.z, m2.z, wm.z); wm.w = fmaf(e4.z, m2.w, wm.w);
            wm.x = fmaf(e4.w, m3.x, wm.x); wm.y = fmaf(e4.w, m3.y, wm.y);
            wm.z = fmaf(e4.w, m3.z, wm.z); wm.w = fmaf(e4.w, m3.w, wm.w);
            esr += e4.x + e4.y + e4.z + e4.w;
        }
    }
    // cross-half combine (half1 -> half0)
    wm.x += __shfl_down_sync(0xffffffff, wm.x, 16);
    wm.y += __shfl_down_sync(0xffffffff, wm.y, 16);
    wm.z += __shfl_down_sync(0xffffffff, wm.z, 16);
    wm.w += __shfl_down_sync(0xffffffff, wm.w, 16);
    esr  += __shfl_down_sync(0xffffffff, esr, 16);
    if (half == 0) {
        float* wmp = g_wmp + ((size_t)(b * 8 + chunk) * 8 + h) * 64;
        *(float4*)&wmp[a0] = wm;
        if ((tid & 31) == 0) g_esp[(b * 8 + chunk) * 8 + h] = esr;
    }
}

// ---------------- K2b: finalize wa ----------------
__global__ void k_wafin(const float* __restrict__ value_w) {
    __shared__ float wm_s[8 * 65];
    __shared__ float es_s[8];
    int b = blockIdx.x;
    int tid = threadIdx.x;   // 64
    for (int i = tid; i < 512; i += 64) {
        const float* p = g_wmp + (size_t)b * 8 * 512 + i;
        float s = 0.f;
#pragma unroll
        for (int c = 0; c < 8; c++) s += p[c * 512];
        wm_s[(i >> 6) * 65 + (i & 63)] = s;
    }
    if (tid < 8) {
        const float* p = g_esp + b * 64 + tid;
        float s = 0.f;
#pragma unroll
        for (int c = 0; c < 8; c++) s += p[c * 8];
        es_s[tid] = s;
    }
    __syncthreads();
    int h = tid >> 3, v = tid & 7;
    float s = 0.f;
#pragma unroll 16
    for (int a = 0; a < 64; a++) s = fmaf(wm_s[h * 65 + a], value_w[a * 8 + v], s);
    g_wa[b * 64 + tid] = s / es_s[h];
}

// ---------------- K3: gate + output; stride-64 + XOR quad swizzle, conflict-free ----------
__device__ __forceinline__ unsigned f2tf(float x) {
    unsigned r; asm("cvt.rna.tf32.f32 %0, %1;" : "=r"(r) : "f"(x)); return r;
}
__device__ __forceinline__ void ldm_x4(unsigned& r0, unsigned& r1, unsigned& r2, unsigned& r3,
                                       unsigned addr) {
    asm volatile("ldmatrix.sync.aligned.m8n8.x4.shared.b16 {%0,%1,%2,%3}, [%4];"
                 : "=r"(r0), "=r"(r1), "=r"(r2), "=r"(r3) : "r"(addr));
}
#define MMA_TF32(C, A0, A1, A2, A3, B0, B1)                                     \
    asm volatile(                                                               \
        "mma.sync.aligned.m16n8k8.row.col.f32.tf32.tf32.f32 "                   \
        "{%0,%1,%2,%3}, {%4,%5,%6,%7}, {%8,%9}, {%0,%1,%2,%3};\n"               \
        : "+f"((C)[0]), "+f"((C)[1]), "+f"((C)[2]), "+f"((C)[3])                \
        : "r"(A0), "r"(A1), "r"(A2), "r"(A3), "r"(B0), "r"(B1))

// logical (row, col) -> physical float index with quad swizzle, stride 64
__device__ __forceinline__ int swz(int row, int col) {
    return row * 64 + ((((col >> 2) ^ (row & 7)) << 2) | (col & 3));
}

#define SMEM_FLOATS (128 * 64 + 64 * 64 + 192)

__global__ __launch_bounds__(256, 4)
void k_main(const float* __restrict__ q_data,
            const float* __restrict__ gating_w,
            const float* __restrict__ gating_b,
            const float* __restrict__ output_w,
            const float* __restrict__ output_b,
            float* __restrict__ out) {
    extern __shared__ float sh[];
    float* qs   = sh;                 // 128 x 64 swizzled: q tile, then gate tile
    float* wb   = sh + 128 * 64;      // 64 x 64 swizzled, transposed [n][k] weights
    float* gb_s = wb + 64 * 64;
    float* ob_s = gb_s + 64;
    float* wa_s = ob_s + 64;

    int b    = blockIdx.y;
    int rt   = blockIdx.x;
    int tid  = threadIdx.x;    // 256: warp w -> rows (w&3)*32, cols (w>>2)*32
    int warp = tid >> 5;
    int lane = tid & 31;
    int g    = lane >> 2;
    int t    = lane & 3;
    int mw   = warp & 3;
    int hN   = warp >> 2;

    if (tid < 64) {
        gb_s[tid] = gating_b[tid];
        ob_s[tid] = output_b[tid];
        wa_s[tid] = g_wa[b * 64 + tid];
    }
    // q tile -> swizzled tf32 smem (float4 per thread, conflict-free)
    const float4* qsrc = (const float4*)(q_data + ((size_t)b * NN + (size_t)rt * 128) * QDIM);
#pragma unroll
    for (int it = 0; it < 8; it++) {
        int i = tid + it * 256;
        float4 v = qsrc[i];
        int r = i >> 4, q16 = i & 15;
        float* d = qs + r * 64 + ((q16 ^ (r & 7)) << 2);
        d[0] = __uint_as_float(f2tf(v.x)); d[1] = __uint_as_float(f2tf(v.y));
        d[2] = __uint_as_float(f2tf(v.z)); d[3] = __uint_as_float(f2tf(v.w));
    }
    // gating_w [k][n] -> wb[n][k] swizzled; lane-consecutive n => coalesced LDG, CF STS
    {
        int n  = tid & 63;
        int kg = (tid >> 6) << 4;    // 16 k's per thread
#pragma unroll
        for (int kk = 0; kk < 16; kk++) {
            int k = kg + kk;
            float v = gating_w[k * 64 + n];
            wb[swz(n, k)] = __uint_as_float(f2tf(v));
        }
    }
    __syncthreads();

    unsigned qs_base = (unsigned)__cvta_generic_to_shared(qs);
    unsigned wb_base = (unsigned)__cvta_generic_to_shared(wb);
    // A: rows mw*32 + (lane&7) + 8*(mi&1) (+16 for mt=1); k-quad sel = mi>>1
    int mi = lane >> 3;
    unsigned a_rb0 = qs_base + (unsigned)(mw * 32 + (lane & 7) + 8 * (mi & 1)) * 256u;
    unsigned a_rb1 = a_rb0 + 16u * 256u;
    unsigned a_xm  = (unsigned)(lane & 7);
    unsigned a_sel = (unsigned)((lane >> 4) & 1);
    // B: n = hN*32 + (bm>>1)*8 + brow (+16 for pair1); sel = bm&1
    int bm = lane >> 3, brow = lane & 7;
    unsigned b_rb0 = wb_base + (unsigned)(hN * 32 + ((bm >> 1) << 3) + brow) * 256u;
    unsigned b_rb1 = b_rb0 + 16u * 256u;
    unsigned b_xm  = (unsigned)brow;
    unsigned b_sel = (unsigned)(bm & 1);

    float c_[2][4][4];
#pragma unroll
    for (int mt = 0; mt < 2; mt++)
#pragma unroll
        for (int nt = 0; nt < 4; nt++)
#pragma unroll
            for (int e = 0; e < 4; e++) c_[mt][nt][e] = 0.f;

    // ---- mma1: S = Q @ Gw ----
#pragma unroll
    for (int k8 = 0; k8 < 8; k8++) {
        unsigned aq = (((unsigned)(k8 * 2) + a_sel) ^ a_xm) << 4;
        unsigned bq = (((unsigned)(k8 * 2) + b_sel) ^ b_xm) << 4;
        unsigned a0[2], a1[2], a2[2], a3[2];
        ldm_x4(a0[0], a1[0], a2[0], a3[0], a_rb0 + aq);
        ldm_x4(a0[1], a1[1], a2[1], a3[1], a_rb1 + aq);
        unsigned p0b0, p0b1, p0c0, p0c1, p1b0, p1b1, p1c0, p1c1;
        ldm_x4(p0b0, p0b1, p0c0, p0c1, b_rb0 + bq);
        ldm_x4(p1b0, p1b1, p1c0, p1c1, b_rb1 + bq);
        MMA_TF32(c_[0][0], a0[0], a1[0], a2[0], a3[0], p0b0, p0b1);
        MMA_TF32(c_[1][0], a0[1], a1[1], a2[1], a3[1], p0b0, p0b1);
        MMA_TF32(c_[0][1], a0[0], a1[0], a2[0], a3[0], p0c0, p0c1);
        MMA_TF32(c_[1][1], a0[1], a1[1], a2[1], a3[1], p0c0, p0c1);
        MMA_TF32(c_[0][2], a0[0], a1[0], a2[0], a3[0], p1b0, p1b1);
        MMA_TF32(c_[1][2], a0[1], a1[1], a2[1], a3[1], p1b0, p1b1);
        MMA_TF32(c_[0][3], a0[0], a1[0], a2[0], a3[0], p1c0, p1c1);
        MMA_TF32(c_[1][3], a0[1], a1[1], a2[1], a3[1], p1c0, p1c1);
    }

    // ---- sigmoid gate -> qs (swizzled tf32), float2 stores ----
#pragma unroll
    for (int mt = 0; mt < 2; mt++) {
        int r0 = mw * 32 + mt * 16;
#pragma unroll
        for (int nt = 0; nt < 4; nt++) {
            int col = hN * 32 + nt * 8 + 2 * t;
            float bb0 = gb_s[col], bb1 = gb_s[col + 1];
            float g0 = 1.f / (1.f + __expf(-(c_[mt][nt][0] + bb0)));
            float g1 = 1.f / (1.f + __expf(-(c_[mt][nt][1] + bb1)));
            float g2 = 1.f / (1.f + __expf(-(c_[mt][nt][2] + bb0)));
            float g3 = 1.f / (1.f + __expf(-(c_[mt][nt][3] + bb1)));
            *(float2*)&qs[swz(r0 + g, col)] =
                make_float2(__uint_as_float(f2tf(g0)), __uint_as_float(f2tf(g1)));
            *(float2*)&qs[swz(r0 + 8 + g, col)] =
                make_float2(__uint_as_float(f2tf(g2)), __uint_as_float(f2tf(g3)));
        }
    }
    __syncthreads();   // all warps done reading wb (Gw), gate fully written
    // ---- W2 = wa (.) output_w -> wb swizzled transposed ----
    {
        int n  = tid & 63;
        int kg = (tid >> 6) << 4;
#pragma unroll
        for (int kk = 0; kk < 16; kk++) {
            int k = kg + kk;
            float v = output_w[k * 64 + n] * wa_s[k];
            wb[swz(n, k)] = __uint_as_float(f2tf(v));
        }
    }
    __syncthreads();

#pragma unroll
    for (int mt = 0; mt < 2; mt++)
#pragma unroll
        for (int nt = 0; nt < 4; nt++)
#pragma unroll
            for (int e = 0; e < 4; e++) c_[mt][nt][e] = 0.f;

    // ---- mma2: out = gate @ W2 ----
#pragma unroll
    for (int k8 = 0; k8 < 8; k8++) {
        unsigned aq = (((unsigned)(k8 * 2) + a_sel) ^ a_xm) << 4;
        unsigned bq = (((unsigned)(k8 * 2) + b_sel) ^ b_xm) << 4;
        unsigned a0[2], a1[2], a2[2], a3[2];
        ldm_x4(a0[0], a1[0], a2[0], a3[0], a_rb0 + aq);
        ldm_x4(a0[1], a1[1], a2[1], a3[1], a_rb1 + aq);
        unsigned p0b0, p0b1, p0c0, p0c1, p1b0, p1b1, p1c0, p1c1;
        ldm_x4(p0b0, p0b1, p0c0, p0c1, b_rb0 + bq);
        ldm_x4(p1b0, p1b1, p1c0, p1c1, b_rb1 + bq);
        MMA_TF32(c_[0][0], a0[0], a1[0], a2[0], a3[0], p0b0, p0b1);
        MMA_TF32(c_[1][0], a0[1], a1[1], a2[1], a3[1], p0b0, p0b1);
        MMA_TF32(c_[0][1], a0[0], a1[0], a2[0], a3[0], p0c0, p0c1);
        MMA_TF32(c_[1][1], a0[1], a1[1], a2[1], a3[1], p0c0, p0c1);
        MMA_TF32(c_[0][2], a0[0], a1[0], a2[0], a3[0], p1b0, p1b1);
        MMA_TF32(c_[1][2], a0[1], a1[1], a2[1], a3[1], p1b0, p1b1);
        MMA_TF32(c_[0][3], a0[0], a1[0], a2[0], a3[0], p1c0, p1c1);
        MMA_TF32(c_[1][3], a0[1], a1[1], a2[1], a3[1], p1c0, p1c1);
    }

    // ---- epilogue ----
    float* outp = out + ((size_t)b * NN + (size_t)rt * 128) * 64;
#pragma unroll
    for (int mt = 0; mt < 2; mt++) {
        int r0 = mw * 32 + mt * 16 + g;
#pragma unroll
        for (int nt = 0; nt < 4; nt++) {
            int col = hN * 32 + nt * 8 + 2 * t;
            float o0 = ob_s[col], o1 = ob_s[col + 1];
            *(float2*)&outp[(size_t)r0 * 64 + col] =
                make_float2(c_[mt][nt][0] + o0, c_[mt][nt][1] + o1);
            *(float2*)&outp[(size_t)(r0 + 8) * 64 + col] =
                make_float2(c_[mt][nt][2] + o0, c_[mt][nt][3] + o1);
        }
    }
}

// ---------------- launch ----------------
extern "C" void kernel_launch(void* const* d_in, const int* in_sizes, int n_in,
                              void* d_out, int out_size) {
    const float* q_data   = (const float*)d_in[0];
    const float* m_data   = (const float*)d_in[1];
    const float* q_mask   = (const float*)d_in[2];
    const float* query_w  = (const float*)d_in[4];
    const float* key_w    = (const float*)d_in[5];
    const float* value_w  = (const float*)d_in[6];
    const float* gating_w = (const float*)d_in[7];
    const float* gating_b = (const float*)d_in[8];
    const float* output_w = (const float*)d_in[9];
    const float* output_b = (const float*)d_in[10];
    float* out = (float*)d_out;

    k_qavg<<<BB * 4, 256>>>(q_data, q_mask);
    k_attn2<<<BB * 8, 256>>>(m_data, q_mask, query_w, key_w);
    k_wafin<<<BB, 64>>>(value_w);

    int smem = SMEM_FLOATS * 4;
    cudaFuncSetAttribute(k_main, cudaFuncAttributeMaxDynamicSharedMemorySize, smem);
    k_main<<<dim3(NN / 128, BB), 256, smem>>>(q_data, gating_w, gating_b,
                                              output_w, output_b, out);
}

// round 13
// speedup vs baseline: 1.1866x; 1.0459x over previous
#include <cuda_runtime.h>
#include <cuda_bf16.h>
#include <math.h>

#define BB 512
#define NN 2048
#define QDIM 64
#define FP16_HUGE 32768.0f

// ---------------- scratch ----------------
__device__ float g_qsum[BB * 4 * 64];
__device__ float g_msum[BB * 4];
__device__ float g_wmp[BB * 8 * 8 * 64];   // [b][chunk][h][a]
__device__ float g_esp[BB * 8 * 64];       // [b][chunk][warp][h]
__device__ float g_wa[BB * 64];

// ---------------- common helpers ----------------
__device__ __forceinline__ unsigned f2tf(float x) {
    unsigned r; asm("cvt.rna.tf32.f32 %0, %1;" : "=r"(r) : "f"(x)); return r;
}
__device__ __forceinline__ void ldm_x4(unsigned& r0, unsigned& r1, unsigned& r2, unsigned& r3,
                                       unsigned addr) {
    asm volatile("ldmatrix.sync.aligned.m8n8.x4.shared.b16 {%0,%1,%2,%3}, [%4];"
                 : "=r"(r0), "=r"(r1), "=r"(r2), "=r"(r3) : "r"(addr));
}
#define MMA_TF32(C, A0, A1, A2, A3, B0, B1)                                     \
    asm volatile(                                                               \
        "mma.sync.aligned.m16n8k8.row.col.f32.tf32.tf32.f32 "                   \
        "{%0,%1,%2,%3}, {%4,%5,%6,%7}, {%8,%9}, {%0,%1,%2,%3};\n"               \
        : "+f"((C)[0]), "+f"((C)[1]), "+f"((C)[2]), "+f"((C)[3])                \
        : "r"(A0), "r"(A1), "r"(A2), "r"(A3), "r"(B0), "r"(B1))

// (row, col) -> physical float index, stride 64, XOR quad swizzle
__device__ __forceinline__ int swz(int row, int col) {
    return row * 64 + ((((col >> 2) ^ (row & 7)) << 2) | (col & 3));
}

// ---------------- K1: partial masked sum of q_data (4 CTAs per batch) ----------------
__global__ void k_qavg(const float* __restrict__ q_data, const float* __restrict__ q_mask) {
    int b   = blockIdx.x >> 2;
    int qtr = blockIdx.x & 3;
    int tid = threadIdx.x;          // 256
    int rg  = tid >> 4;
    int cq  = (tid & 15) << 2;
    int n0  = qtr * 512;
    const float* qb = q_data + (size_t)b * NN * QDIM;
    const float* mb = q_mask + (size_t)b * NN;
    float4 acc = make_float4(0.f, 0.f, 0.f, 0.f);
    float ms = 0.f;
#pragma unroll 4
    for (int n = n0 + rg; n < n0 + 512; n += 32) {
        float m0 = mb[n];
        float m1 = mb[n + 16];
        float4 a = *(const float4*)&qb[(size_t)n * QDIM + cq];
        float4 c = *(const float4*)&qb[(size_t)(n + 16) * QDIM + cq];
        acc.x = fmaf(m0, a.x, acc.x); acc.y = fmaf(m0, a.y, acc.y);
        acc.z = fmaf(m0, a.z, acc.z); acc.w = fmaf(m0, a.w, acc.w);
        acc.x = fmaf(m1, c.x, acc.x); acc.y = fmaf(m1, c.y, acc.y);
        acc.z = fmaf(m1, c.z, acc.z); acc.w = fmaf(m1, c.w, acc.w);
        ms += m0 + m1;
    }
    __shared__ float4 sa[16][16];
    __shared__ float  sm[16];
    sa[rg][tid & 15] = acc;
    if ((tid & 15) == 0) sm[rg] = ms;
    __syncthreads();
    if (tid < 16) {
        float4 t = make_float4(0.f, 0.f, 0.f, 0.f);
        float msum = 0.f;
#pragma unroll
        for (int r = 0; r < 16; r++) {
            float4 v = sa[r][tid];
            t.x += v.x; t.y += v.y; t.z += v.z; t.w += v.w;
            msum += sm[r];
        }
        float* dst = g_qsum + (b * 4 + qtr) * 64 + tid * 4;
        dst[0] = t.x; dst[1] = t.y; dst[2] = t.z; dst[3] = t.w;
        if (tid == 0) g_msum[b * 4 + qtr] = msum;
    }
}

// ---------------- K2: attention via tensor cores, 8 chunks/batch (2 tiles each) --------
// e-phase:  logits[128x8] = ms[128x64] @ qk^T   (B = qk_hs[h][a], preloaded regs)
// wm-phase: wm[16(8 real)x64] += es[16x128] @ ms[128x64]
__global__ __launch_bounds__(256)
void k_attn2(const float* __restrict__ m_data,
             const float* __restrict__ q_mask,
             const float* __restrict__ query_w,
             const float* __restrict__ key_w) {
    __shared__ __align__(16) float ms[128 * 64];    // tf32, swizzled
    __shared__ __align__(16) float es[16 * 128];    // tf32, swizzled (rows 8-15 zero)
    __shared__ __align__(16) float qk_hs[8 * 64];   // tf32 [h][a]
    __shared__ float qh_s[64];
    __shared__ float qa_s[64];
    __shared__ float msk[128];

    int b     = blockIdx.x >> 3;
    int chunk = blockIdx.x & 7;
    int tid   = threadIdx.x;   // 256
    int warp  = tid >> 5;
    int lane  = tid & 31;
    int g     = lane >> 2;
    int t     = lane & 3;

    if (tid < 64) {
        float msum = g_msum[b * 4] + g_msum[b * 4 + 1] + g_msum[b * 4 + 2] + g_msum[b * 4 + 3];
        const float* qp = g_qsum + b * 256 + tid;
        qa_s[tid] = (qp[0] + qp[64] + qp[128] + qp[192]) / (msum + 1e-10f);
    }
    __syncthreads();
    if (tid < 64) {
        float s = 0.f;
#pragma unroll 16
        for (int d = 0; d < 64; d++) s = fmaf(qa_s[d], query_w[d * 64 + tid], s);
        qh_s[tid] = s * 0.35355339059327373f;   // KD^-0.5
    }
    __syncthreads();
    // qk_hs[h][a] = sum_c key_w[a][c] * qh[h][c]  (tf32)
#pragma unroll
    for (int it = 0; it < 2; it++) {
        int i = tid + it * 256;
        int h = i >> 6, a = i & 63;
        float s = 0.f;
#pragma unroll
        for (int c = 0; c < 8; c++) s = fmaf(key_w[a * 8 + c], qh_s[h * 8 + c], s);
        qk_hs[h * 64 + a] = __uint_as_float(f2tf(s));
    }
    // zero es rows 8..15
    for (int i = tid; i < 8 * 128; i += 256) es[8 * 128 + i] = 0.f;
    __syncthreads();

    // preload B fragments for e-phase (loop-invariant): b0=qk_hs[g][k8*8+t], b1=+4
    unsigned bq[8][2];
#pragma unroll
    for (int k8 = 0; k8 < 8; k8++) {
        bq[k8][0] = __float_as_uint(qk_hs[g * 64 + k8 * 8 + t]);
        bq[k8][1] = __float_as_uint(qk_hs[g * 64 + k8 * 8 + t + 4]);
    }

    unsigned ms_base = (unsigned)__cvta_generic_to_shared(ms);
    unsigned es_base = (unsigned)__cvta_generic_to_shared(es);
    int mi = lane >> 3;
    unsigned a_rb = ms_base + (unsigned)(warp * 16 + (lane & 7) + 8 * (mi & 1)) * 256u;
    unsigned a_sel = (unsigned)((lane >> 4) & 1);
    unsigned a_xm  = (unsigned)(lane & 7);
    unsigned e_rb = es_base + (unsigned)((lane & 7) + 8 * (mi & 1)) * 512u;  // es stride 128 fl

    float cw[4] = {0.f, 0.f, 0.f, 0.f};   // wm accumulator (persists across tiles)
    float esr0 = 0.f, esr1 = 0.f;

    const float* mb = q_mask + (size_t)b * NN;

    for (int tile = chunk * 2; tile < chunk * 2 + 2; tile++) {
        __syncthreads();   // prev wm-phase done with ms/es
        // load ms (tf32, swizzled)
        const float4* msrc = (const float4*)(m_data + ((size_t)b * NN + tile * 128) * 64);
#pragma unroll
        for (int it = 0; it < 8; it++) {
            int i = tid + it * 256;
            float4 v = msrc[i];
            int r = i >> 4, q16 = i & 15;
            float* d = ms + r * 64 + ((q16 ^ (r & 7)) << 2);
            d[0] = __uint_as_float(f2tf(v.x)); d[1] = __uint_as_float(f2tf(v.y));
            d[2] = __uint_as_float(f2tf(v.z)); d[3] = __uint_as_float(f2tf(v.w));
        }
        if (tid < 128) msk[tid] = mb[tile * 128 + tid];
        __syncthreads();
        // ---- e-phase: warp owns rows warp*16..+15 ----
        {
            float cl[4] = {0.f, 0.f, 0.f, 0.f};
#pragma unroll
            for (int k8 = 0; k8 < 8; k8++) {
                unsigned aq = (((unsigned)(k8 * 2) + a_sel) ^ a_xm) << 4;
                unsigned a0, a1, a2, a3;
                ldm_x4(a0, a1, a2, a3, a_rb + aq);
                MMA_TF32(cl, a0, a1, a2, a3, bq[k8][0], bq[k8][1]);
            }
            int row = warp * 16 + g;
            float mb0 = FP16_HUGE * (msk[row] - 1.0f);
            float mb1 = FP16_HUGE * (msk[row + 8] - 1.0f);
            float e0 = __expf(cl[0] + mb0);   // (h=2t,   n=row)
            float e1 = __expf(cl[1] + mb0);   // (h=2t+1, n=row)
            float e2 = __expf(cl[2] + mb1);   // (h=2t,   n=row+8)
            float e3 = __expf(cl[3] + mb1);   // (h=2t+1, n=row+8)
            esr0 += e0 + e2;
            esr1 += e1 + e3;
            int h0 = 2 * t, h1 = 2 * t + 1;
            // es stride 128, quad swizzle on token index
            es[h0 * 128 + ((((row >> 2) ^ h0) << 2) | (row & 3))] = __uint_as_float(f2tf(e0));
            es[h1 * 128 + ((((row >> 2) ^ h1) << 2) | (row & 3))] = __uint_as_float(f2tf(e1));
            int r8 = row + 8;
            es[h0 * 128 + ((((r8 >> 2) ^ h0) << 2) | (r8 & 3))] = __uint_as_float(f2tf(e2));
            es[h1 * 128 + ((((r8 >> 2) ^ h1) << 2) | (r8 & 3))] = __uint_as_float(f2tf(e3));
        }
        __syncthreads();
        // ---- wm-phase: warp owns a-cols warp*8..+7; K = 128 tokens ----
        {
            int a = warp * 8 + g;
#pragma unroll
            for (int k8 = 0; k8 < 16; k8++) {
                unsigned eq = (((unsigned)(k8 * 2) + a_sel) ^ a_xm) << 4;
                unsigned ea0, ea1, ea2, ea3;
                ldm_x4(ea0, ea1, ea2, ea3, e_rb + eq);
                int tok0 = k8 * 8 + t, tok1 = tok0 + 4;
                unsigned b0 = __float_as_uint(
                    ms[tok0 * 64 + ((((a >> 2) ^ (tok0 & 7)) << 2) | (a & 3))]);
                unsigned b1 = __float_as_uint(
                    ms[tok1 * 64 + ((((a >> 2) ^ (tok1 & 7)) << 2) | (a & 3))]);
                MMA_TF32(cw, ea0, ea1, ea2, ea3, b0, b1);
            }
        }
    }
    // write wm partials: lane(g,t) holds wm[h=g][a = warp*8 + 2t, 2t+1]
    {
        float* wmp = g_wmp + ((size_t)(b * 8 + chunk)) * 512;
        *(float2*)&wmp[g * 64 + warp * 8 + 2 * t] = make_float2(cw[0], cw[1]);
    }
    // esum partials: reduce over g (lane bits 2..4)
    esr0 += __shfl_xor_sync(0xffffffff, esr0, 4);
    esr0 += __shfl_xor_sync(0xffffffff, esr0, 8);
    esr0 += __shfl_xor_sync(0xffffffff, esr0, 16);
    esr1 += __shfl_xor_sync(0xffffffff, esr1, 4);
    esr1 += __shfl_xor_sync(0xffffffff, esr1, 8);
    esr1 += __shfl_xor_sync(0xffffffff, esr1, 16);
    if (lane < 4) {
        float* ep = g_esp + ((size_t)(b * 8 + chunk)) * 64 + warp * 8;
        ep[2 * lane]     = esr0;
        ep[2 * lane + 1] = esr1;
    }
}

// ---------------- K2b: finalize wa = (sum wm) @ value_w / esum ----------------
__global__ void k_wafin(const float* __restrict__ value_w) {
    __shared__ float wm_s[8 * 65];
    __shared__ float es_s[8];
    int b = blockIdx.x;
    int tid = threadIdx.x;   // 64
    for (int i = tid; i < 512; i += 64) {
        const float* p = g_wmp + (size_t)b * 8 * 512 + i;
        float s = 0.f;
#pragma unroll
        for (int c = 0; c < 8; c++) s += p[c * 512];
        wm_s[(i >> 6) * 65 + (i & 63)] = s;
    }
    if (tid < 8) {
        const float* p = g_esp + (size_t)b * 512 + tid;
        float s = 0.f;
#pragma unroll
        for (int j = 0; j < 64; j++) s += p[j * 8];
        es_s[tid] = s;
    }
    __syncthreads();
    int h = tid >> 3, v = tid & 7;
    float s = 0.f;
#pragma unroll 16
    for (int a = 0; a < 64; a++) s = fmaf(wm_s[h * 65 + a], value_w[a * 8 + v], s);
    g_wa[b * 64 + tid] = s / es_s[h];
}

// ---------------- K3: gate + output (swizzled + CF float4 wb build) ----------------
#define SMEM_FLOATS (128 * 64 + 64 * 64 + 192)

__global__ __launch_bounds__(256, 4)
void k_main(const float* __restrict__ q_data,
            const float* __restrict__ gating_w,
            const float* __restrict__ gating_b,
            const float* __restrict__ output_w,
            const float* __restrict__ output_b,
            float* __restrict__ out) {
    extern __shared__ float sh[];
    float* qs   = sh;                 // 128 x 64 swizzled: q tile, then gate tile
    float* wb   = sh + 128 * 64;      // 64 x 64 swizzled, transposed [n][k]
    float* gb_s = wb + 64 * 64;
    float* ob_s = gb_s + 64;
    float* wa_s = ob_s + 64;

    int b    = blockIdx.y;
    int rt   = blockIdx.x;
    int tid  = threadIdx.x;    // 256
    int warp = tid >> 5;
    int lane = tid & 31;
    int g    = lane >> 2;
    int t    = lane & 3;
    int mw   = warp & 3;
    int hN   = warp >> 2;

    if (tid < 64) {
        gb_s[tid] = gating_b[tid];
        ob_s[tid] = output_b[tid];
        wa_s[tid] = g_wa[b * 64 + tid];
    }
    const float4* qsrc = (const float4*)(q_data + ((size_t)b * NN + (size_t)rt * 128) * QDIM);
#pragma unroll
    for (int it = 0; it < 8; it++) {
        int i = tid + it * 256;
        float4 v = qsrc[i];
        int r = i >> 4, q16 = i & 15;
        float* d = qs + r * 64 + ((q16 ^ (r & 7)) << 2);
        d[0] = __uint_as_float(f2tf(v.x)); d[1] = __uint_as_float(f2tf(v.y));
        d[2] = __uint_as_float(f2tf(v.z)); d[3] = __uint_as_float(f2tf(v.w));
    }
    // gating_w [k][n] -> wb[n][k] swizzled; float4 STS, conflict-free
    {
        int n   = tid & 63;
        int kq4 = tid >> 6;          // 4 quads per thread
#pragma unroll
        for (int qq = 0; qq < 4; qq++) {
            int quad = kq4 * 4 + qq;
            int k0 = quad * 4;
            float4 v;
            v.x = __uint_as_float(f2tf(gating_w[(k0 + 0) * 64 + n]));
            v.y = __uint_as_float(f2tf(gating_w[(k0 + 1) * 64 + n]));
            v.z = __uint_as_float(f2tf(gating_w[(k0 + 2) * 64 + n]));
            v.w = __uint_as_float(f2tf(gating_w[(k0 + 3) * 64 + n]));
            *(float4*)&wb[n * 64 + ((quad ^ (n & 7)) << 2)] = v;
        }
    }
    __syncthreads();

    unsigned qs_base = (unsigned)__cvta_generic_to_shared(qs);
    unsigned wb_base = (unsigned)__cvta_generic_to_shared(wb);
    int mi = lane >> 3;
    unsigned a_rb0 = qs_base + (unsigned)(mw * 32 + (lane & 7) + 8 * (mi & 1)) * 256u;
    unsigned a_rb1 = a_rb0 + 16u * 256u;
    unsigned a_xm  = (unsigned)(lane & 7);
    unsigned a_sel = (unsigned)((lane >> 4) & 1);
    int bm = lane >> 3, brow = lane & 7;
    unsigned b_rb0 = wb_base + (unsigned)(hN * 32 + ((bm >> 1) << 3) + brow) * 256u;
    unsigned b_rb1 = b_rb0 + 16u * 256u;
    unsigned b_xm  = (unsigned)brow;
    unsigned b_sel = (unsigned)(bm & 1);

    float c_[2][4][4];
#pragma unroll
    for (int mt = 0; mt < 2; mt++)
#pragma unroll
        for (int nt = 0; nt < 4; nt++)
#pragma unroll
            for (int e = 0; e < 4; e++) c_[mt][nt][e] = 0.f;

    // ---- mma1: S = Q @ Gw ----
#pragma unroll
    for (int k8 = 0; k8 < 8; k8++) {
        unsigned aq = (((unsigned)(k8 * 2) + a_sel) ^ a_xm) << 4;
        unsigned bq = (((unsigned)(k8 * 2) + b_sel) ^ b_xm) << 4;
        unsigned a0[2], a1[2], a2[2], a3[2];
        ldm_x4(a0[0], a1[0], a2[0], a3[0], a_rb0 + aq);
        ldm_x4(a0[1], a1[1], a2[1], a3[1], a_rb1 + aq);
        unsigned p0b0, p0b1, p0c0, p0c1, p1b0, p1b1, p1c0, p1c1;
        ldm_x4(p0b0, p0b1, p0c0, p0c1, b_rb0 + bq);
        ldm_x4(p1b0, p1b1, p1c0, p1c1, b_rb1 + bq);
        MMA_TF32(c_[0][0], a0[0], a1[0], a2[0], a3[0], p0b0, p0b1);
        MMA_TF32(c_[1][0], a0[1], a1[1], a2[1], a3[1], p0b0, p0b1);
        MMA_TF32(c_[0][1], a0[0], a1[0], a2[0], a3[0], p0c0, p0c1);
        MMA_TF32(c_[1][1], a0[1], a1[1], a2[1], a3[1], p0c0, p0c1);
        MMA_TF32(c_[0][2], a0[0], a1[0], a2[0], a3[0], p1b0, p1b1);
        MMA_TF32(c_[1][2], a0[1], a1[1], a2[1], a3[1], p1b0, p1b1);
        MMA_TF32(c_[0][3], a0[0], a1[0], a2[0], a3[0], p1c0, p1c1);
        MMA_TF32(c_[1][3], a0[1], a1[1], a2[1], a3[1], p1c0, p1c1);
    }

    // ---- sigmoid gate -> qs (swizzled tf32) ----
#pragma unroll
    for (int mt = 0; mt < 2; mt++) {
        int r0 = mw * 32 + mt * 16;
#pragma unroll
        for (int nt = 0; nt < 4; nt++) {
            int col = hN * 32 + nt * 8 + 2 * t;
            float bb0 = gb_s[col], bb1 = gb_s[col + 1];
            float g0 = 1.f / (1.f + __expf(-(c_[mt][nt][0] + bb0)));
            float g1 = 1.f / (1.f + __expf(-(c_[mt][nt][1] + bb1)));
            float g2 = 1.f / (1.f + __expf(-(c_[mt][nt][2] + bb0)));
            float g3 = 1.f / (1.f + __expf(-(c_[mt][nt][3] + bb1)));
            *(float2*)&qs[swz(r0 + g, col)] =
                make_float2(__uint_as_float(f2tf(g0)), __uint_as_float(f2tf(g1)));
            *(float2*)&qs[swz(r0 + 8 + g, col)] =
                make_float2(__uint_as_float(f2tf(g2)), __uint_as_float(f2tf(g3)));
        }
    }
    __syncthreads();
    // ---- W2 = wa (.) output_w -> wb (float4 CF) ----
    {
        int n   = tid & 63;
        int kq4 = tid >> 6;
#pragma unroll
        for (int qq = 0; qq < 4; qq++) {
            int quad = kq4 * 4 + qq;
            int k0 = quad * 4;
            float4 v;
            v.x = __uint_as_float(f2tf(output_w[(k0 + 0) * 64 + n] * wa_s[k0 + 0]));
            v.y = __uint_as_float(f2tf(output_w[(k0 + 1) * 64 + n] * wa_s[k0 + 1]));
            v.z = __uint_as_float(f2tf(output_w[(k0 + 2) * 64 + n] * wa_s[k0 + 2]));
            v.w = __uint_as_float(f2tf(output_w[(k0 + 3) * 64 + n] * wa_s[k0 + 3]));
            *(float4*)&wb[n * 64 + ((quad ^ (n & 7)) << 2)] = v;
        }
    }
    __syncthreads();

#pragma unroll
    for (int mt = 0; mt < 2; mt++)
#pragma unroll
        for (int nt = 0; nt < 4; nt++)
#pragma unroll
            for (int e = 0; e < 4; e++) c_[mt][nt][e] = 0.f;

    // ---- mma2: out = gate @ W2 ----
#pragma unroll
    for (int k8 = 0; k8 < 8; k8++) {
        unsigned aq = (((unsigned)(k8 * 2) + a_sel) ^ a_xm) << 4;
        unsigned bq = (((unsigned)(k8 * 2) + b_sel) ^ b_xm) << 4;
        unsigned a0[2], a1[2], a2[2], a3[2];
        ldm_x4(a0[0], a1[0], a2[0], a3[0], a_rb0 + aq);
        ldm_x4(a0[1], a1[1], a2[1], a3[1], a_rb1 + aq);
        unsigned p0b0, p0b1, p0c0, p0c1, p1b0, p1b1, p1c0, p1c1;
        ldm_x4(p0b0, p0b1, p0c0, p0c1, b_rb0 + bq);
        ldm_x4(p1b0, p1b1, p1c0, p1c1, b_rb1 + bq);
        MMA_TF32(c_[0][0], a0[0], a1[0], a2[0], a3[0], p0b0, p0b1);
        MMA_TF32(c_[1][0], a0[1], a1[1], a2[1], a3[1], p0b0, p0b1);
        MMA_TF32(c_[0][1], a0[0], a1[0], a2[0], a3[0], p0c0, p0c1);
        MMA_TF32(c_[1][1], a0[1], a1[1], a2[1], a3[1], p0c0, p0c1);
        MMA_TF32(c_[0][2], a0[0], a1[0], a2[0], a3[0], p1b0, p1b1);
        MMA_TF32(c_[1][2], a0[1], a1[1], a2[1], a3[1], p1b0, p1b1);
        MMA_TF32(c_[0][3], a0[0], a1[0], a2[0], a3[0], p1c0, p1c1);
        MMA_TF32(c_[1][3], a0[1], a1[1], a2[1], a3[1], p1c0, p1c1);
    }

    // ---- epilogue ----
    float* outp = out + ((size_t)b * NN + (size_t)rt * 128) * 64;
#pragma unroll
    for (int mt = 0; mt < 2; mt++) {
        int r0 = mw * 32 + mt * 16 + g;
#pragma unroll
        for (int nt = 0; nt < 4; nt++) {
            int col = hN * 32 + nt * 8 + 2 * t;
            float o0 = ob_s[col], o1 = ob_s[col + 1];
            *(float2*)&outp[(size_t)r0 * 64 + col] =
                make_float2(c_[mt][nt][0] + o0, c_[mt][nt][1] + o1);
            *(float2*)&outp[(size_t)(r0 + 8) * 64 + col] =
                make_float2(c_[mt][nt][2] + o0, c_[mt][nt][3] + o1);
        }
    }
}

// ---------------- launch ----------------
extern "C" void kernel_launch(void* const* d_in, const int* in_sizes, int n_in,
                              void* d_out, int out_size) {
    const float* q_data   = (const float*)d_in[0];
    const float* m_data   = (const float*)d_in[1];
    const float* q_mask   = (const float*)d_in[2];
    const float* query_w  = (const float*)d_in[4];
    const float* key_w    = (const float*)d_in[5];
    const float* value_w  = (const float*)d_in[6];
    const float* gating_w = (const float*)d_in[7];
    const float* gating_b = (const float*)d_in[8];
    const float* output_w = (const float*)d_in[9];
    const float* output_b = (const float*)d_in[10];
    float* out = (float*)d_out;

    k_qavg<<<BB * 4, 256>>>(q_data, q_mask);
    k_attn2<<<BB * 8, 256>>>(m_data, q_mask, query_w, key_w);
    k_wafin<<<BB, 64>>>(value_w);

    int smem = SMEM_FLOATS * 4;
    cudaFuncSetAttribute(k_main, cudaFuncAttributeMaxDynamicSharedMemorySize, smem);
    k_main<<<dim3(NN / 128, BB), 256, smem>>>(q_data, gating_w, gating_b,
                                              output_w, output_b, out);
}

// round 15
// speedup vs baseline: 1.2294x; 1.0361x over previous
#include <cuda_runtime.h>
#include <cuda_bf16.h>
#include <math.h>

#define BB 512
#define NN 2048
#define QDIM 64
#define FP16_HUGE 32768.0f

// ---------------- scratch ----------------
__device__ float g_qsum[BB * 4 * 64];
__device__ float g_msum[BB * 4];
__device__ float g_qk[BB * 8 * 64];          // tf32 [b][h][a]
__device__ float g_wmp[BB * 16 * 8 * 64];    // [b][chunk][h][a]
__device__ float g_esp[BB * 16 * 64];        // [b][chunk][warp][h]
__device__ float g_gwimg[64 * 64];           // swizzled tf32 Gw image
__device__ float g_w2img[BB * 64 * 64];      // swizzled tf32 W2 image per batch

// ---------------- common helpers ----------------
__device__ __forceinline__ unsigned f2tf(float x) {
    unsigned r; asm("cvt.rna.tf32.f32 %0, %1;" : "=r"(r) : "f"(x)); return r;
}
__device__ __forceinline__ void ldm_x4(unsigned& r0, unsigned& r1, unsigned& r2, unsigned& r3,
                                       unsigned addr) {
    asm volatile("ldmatrix.sync.aligned.m8n8.x4.shared.b16 {%0,%1,%2,%3}, [%4];"
                 : "=r"(r0), "=r"(r1), "=r"(r2), "=r"(r3) : "r"(addr));
}
#define MMA_TF32(C, A0, A1, A2, A3, B0, B1)                                     \
    asm volatile(                                                               \
        "mma.sync.aligned.m16n8k8.row.col.f32.tf32.tf32.f32 "                   \
        "{%0,%1,%2,%3}, {%4,%5,%6,%7}, {%8,%9}, {%0,%1,%2,%3};\n"               \
        : "+f"((C)[0]), "+f"((C)[1]), "+f"((C)[2]), "+f"((C)[3])                \
        : "r"(A0), "r"(A1), "r"(A2), "r"(A3), "r"(B0), "r"(B1))

// (row, col) -> physical float index, stride 64, XOR quad swizzle
__device__ __forceinline__ int swz(int row, int col) {
    return row * 64 + ((((col >> 2) ^ (row & 7)) << 2) | (col & 3));
}

// ---------------- K0: swizzled tf32 image of gating_w (once) ----------------
__global__ void k_gwprep(const float* __restrict__ gating_w) {
    int tid = threadIdx.x;   // 256
#pragma unroll
    for (int j = 0; j < 16; j++) {
        int idx = j * 256 + tid;          // physical linear index
        int n = idx >> 6, pc = idx & 63;
        int quad = (pc >> 2) ^ (n & 7);   // logical quad
        int k = quad * 4 + (idx & 3);
        g_gwimg[idx] = __uint_as_float(f2tf(gating_w[k * 64 + n]));
    }
}

// ---------------- K1: partial masked sum of q_data (4 CTAs per batch) ----------------
__global__ void k_qavg(const float* __restrict__ q_data, const float* __restrict__ q_mask) {
    int b   = blockIdx.x >> 2;
    int qtr = blockIdx.x & 3;
    int tid = threadIdx.x;          // 256
    int rg  = tid >> 4;
    int cq  = (tid & 15) << 2;
    int n0  = qtr * 512;
    const float* qb = q_data + (size_t)b * NN * QDIM;
    const float* mb = q_mask + (size_t)b * NN;
    float4 acc = make_float4(0.f, 0.f, 0.f, 0.f);
    float ms = 0.f;
#pragma unroll 4
    for (int n = n0 + rg; n < n0 + 512; n += 32) {
        float m0 = mb[n];
        float m1 = mb[n + 16];
        float4 a = *(const float4*)&qb[(size_t)n * QDIM + cq];
        float4 c = *(const float4*)&qb[(size_t)(n + 16) * QDIM + cq];
        acc.x = fmaf(m0, a.x, acc.x); acc.y = fmaf(m0, a.y, acc.y);
        acc.z = fmaf(m0, a.z, acc.z); acc.w = fmaf(m0, a.w, acc.w);
        acc.x = fmaf(m1, c.x, acc.x); acc.y = fmaf(m1, c.y, acc.y);
        acc.z = fmaf(m1, c.z, acc.z); acc.w = fmaf(m1, c.w, acc.w);
        ms += m0 + m1;
    }
    __shared__ float4 sa[16][16];
    __shared__ float  sm[16];
    sa[rg][tid & 15] = acc;
    if ((tid & 15) == 0) sm[rg] = ms;
    __syncthreads();
    if (tid < 16) {
        float4 t = make_float4(0.f, 0.f, 0.f, 0.f);
        float msum = 0.f;
#pragma unroll
        for (int r = 0; r < 16; r++) {
            float4 v = sa[r][tid];
            t.x += v.x; t.y += v.y; t.z += v.z; t.w += v.w;
            msum += sm[r];
        }
        float* dst = g_qsum + (b * 4 + qtr) * 64 + tid * 4;
        dst[0] = t.x; dst[1] = t.y; dst[2] = t.z; dst[3] = t.w;
        if (tid == 0) g_msum[b * 4 + qtr] = msum;
    }
}

// ---------------- K1b: per-batch projected queries qk[h][a] (tf32) ----------------
__global__ void k_qk(const float* __restrict__ query_w, const float* __restrict__ key_w) {
    __shared__ float qa_s[64];
    __shared__ float qh_s[64];
    int b = blockIdx.x;
    int tid = threadIdx.x;   // 64
    {
        float msum = g_msum[b * 4] + g_msum[b * 4 + 1] + g_msum[b * 4 + 2] + g_msum[b * 4 + 3];
        const float* qp = g_qsum + b * 256 + tid;
        qa_s[tid] = (qp[0] + qp[64] + qp[128] + qp[192]) / (msum + 1e-10f);
    }
    __syncthreads();
    {
        float s = 0.f;
#pragma unroll 16
        for (int d = 0; d < 64; d++) s = fmaf(qa_s[d], query_w[d * 64 + tid], s);
        qh_s[tid] = s * 0.35355339059327373f;   // KD^-0.5
    }
    __syncthreads();
    int a = tid;
#pragma unroll
    for (int h = 0; h < 8; h++) {
        float s = 0.f;
#pragma unroll
        for (int c = 0; c < 8; c++) s = fmaf(key_w[a * 8 + c], qh_s[h * 8 + c], s);
        g_qk[b * 512 + h * 64 + a] = __uint_as_float(f2tf(s));
    }
}

// ---------------- K2: attention via tensor cores, 16 chunks/batch (1 tile each) --------
__global__ __launch_bounds__(256)
void k_attn2(const float* __restrict__ m_data, const float* __restrict__ q_mask) {
    __shared__ __align__(16) float ms[128 * 64];    // tf32, swizzled
    __shared__ __align__(16) float es[16 * 128];    // tf32, swizzled (rows 8-15 zero)
    __shared__ float msk[128];

    int b     = blockIdx.x >> 4;
    int chunk = blockIdx.x & 15;
    int tid   = threadIdx.x;   // 256
    int warp  = tid >> 5;
    int lane  = tid & 31;
    int g     = lane >> 2;
    int t     = lane & 3;

    // preload B fragments for e-phase from precomputed qk (L2-hot)
    unsigned bq[8][2];
    {
        const float* qkp = g_qk + b * 512 + g * 64 + t;
#pragma unroll
        for (int k8 = 0; k8 < 8; k8++) {
            bq[k8][0] = __float_as_uint(qkp[k8 * 8]);
            bq[k8][1] = __float_as_uint(qkp[k8 * 8 + 4]);
        }
    }
    // zero es rows 8..15
#pragma unroll
    for (int j = 0; j < 4; j++) es[1024 + j * 256 + tid] = 0.f;

    // load ms (tf32, swizzled)
    {
        const float4* msrc = (const float4*)(m_data + ((size_t)b * NN + chunk * 128) * 64);
#pragma unroll
        for (int it = 0; it < 8; it++) {
            int i = tid + it * 256;
            float4 v = msrc[i];
            int r = i >> 4, q16 = i & 15;
            float* d = ms + r * 64 + ((q16 ^ (r & 7)) << 2);
            d[0] = __uint_as_float(f2tf(v.x)); d[1] = __uint_as_float(f2tf(v.y));
            d[2] = __uint_as_float(f2tf(v.z)); d[3] = __uint_as_float(f2tf(v.w));
        }
        if (tid < 128) msk[tid] = q_mask[(size_t)b * NN + chunk * 128 + tid];
    }
    __syncthreads();

    unsigned ms_base = (unsigned)__cvta_generic_to_shared(ms);
    unsigned es_base = (unsigned)__cvta_generic_to_shared(es);
    int mi = lane >> 3;
    unsigned a_rb  = ms_base + (unsigned)(warp * 16 + (lane & 7) + 8 * (mi & 1)) * 256u;
    unsigned a_sel = (unsigned)((lane >> 4) & 1);
    unsigned a_xm  = (unsigned)(lane & 7);
    unsigned e_rb  = es_base + (unsigned)((lane & 7) + 8 * (mi & 1)) * 512u;

    float esr0 = 0.f, esr1 = 0.f;

    // ---- e-phase: warp owns rows warp*16..+15 ----
    {
        float cl[4] = {0.f, 0.f, 0.f, 0.f};
#pragma unroll
        for (int k8 = 0; k8 < 8; k8++) {
            unsigned aq = (((unsigned)(k8 * 2) + a_sel) ^ a_xm) << 4;
            unsigned a0, a1, a2, a3;
            ldm_x4(a0, a1, a2, a3, a_rb + aq);
            MMA_TF32(cl, a0, a1, a2, a3, bq[k8][0], bq[k8][1]);
        }
        int row = warp * 16 + g;
        float mb0 = FP16_HUGE * (msk[row] - 1.0f);
        float mb1 = FP16_HUGE * (msk[row + 8] - 1.0f);
        float e0 = __expf(cl[0] + mb0);
        float e1 = __expf(cl[1] + mb0);
        float e2 = __expf(cl[2] + mb1);
        float e3 = __expf(cl[3] + mb1);
        esr0 += e0 + e2;
        esr1 += e1 + e3;
        int h0 = 2 * t, h1 = 2 * t + 1;
        es[h0 * 128 + ((((row >> 2) ^ h0) << 2) | (row & 3))] = __uint_as_float(f2tf(e0));
        es[h1 * 128 + ((((row >> 2) ^ h1) << 2) | (row & 3))] = __uint_as_float(f2tf(e1));
        int r8 = row + 8;
        es[h0 * 128 + ((((r8 >> 2) ^ h0) << 2) | (r8 & 3))] = __uint_as_float(f2tf(e2));
        es[h1 * 128 + ((((r8 >> 2) ^ h1) << 2) | (r8 & 3))] = __uint_as_float(f2tf(e3));
    }
    __syncthreads();
    // ---- wm-phase: warp owns a-cols warp*8..+7 ----
    float cw[4] = {0.f, 0.f, 0.f, 0.f};
    {
        int a = warp * 8 + g;
#pragma unroll
        for (int k8 = 0; k8 < 16; k8++) {
            unsigned eq = (((unsigned)(k8 * 2) + a_sel) ^ a_xm) << 4;
            unsigned ea0, ea1, ea2, ea3;
            ldm_x4(ea0, ea1, ea2, ea3, e_rb + eq);
            int tok0 = k8 * 8 + t, tok1 = tok0 + 4;
            unsigned b0 = __float_as_uint(
                ms[tok0 * 64 + ((((a >> 2) ^ (tok0 & 7)) << 2) | (a & 3))]);
            unsigned b1 = __float_as_uint(
                ms[tok1 * 64 + ((((a >> 2) ^ (tok1 & 7)) << 2) | (a & 3))]);
            MMA_TF32(cw, ea0, ea1, ea2, ea3, b0, b1);
        }
    }
    // write wm partials: lane(g,t) holds wm[h=g][a = warp*8 + 2t, 2t+1]
    {
        float* wmp = g_wmp + ((size_t)(b * 16 + chunk)) * 512;
        *(float2*)&wmp[g * 64 + warp * 8 + 2 * t] = make_float2(cw[0], cw[1]);
    }
    // esum partials: reduce over g (lane bits 2..4)
    esr0 += __shfl_xor_sync(0xffffffff, esr0, 4);
    esr0 += __shfl_xor_sync(0xffffffff, esr0, 8);
    esr0 += __shfl_xor_sync(0xffffffff, esr0, 16);
    esr1 += __shfl_xor_sync(0xffffffff, esr1, 4);
    esr1 += __shfl_xor_sync(0xffffffff, esr1, 8);
    esr1 += __shfl_xor_sync(0xffffffff, esr1, 16);
    if (lane < 4) {
        float* ep = g_esp + ((size_t)(b * 16 + chunk)) * 64 + warp * 8;
        ep[2 * lane]     = esr0;
        ep[2 * lane + 1] = esr1;
    }
}

// ---------------- K2b: finalize wa; build per-batch W2 swizzled image ----------------
__global__ void k_wafin(const float* __restrict__ value_w,
                        const float* __restrict__ output_w) {
    __shared__ float wm_s[8 * 65];
    __shared__ float es_s[8];
    __shared__ float wa_f[64];
    int b = blockIdx.x;
    int tid = threadIdx.x;   // 256
    for (int i = tid; i < 512; i += 256) {
        const float* p = g_wmp + (size_t)b * 16 * 512 + i;
        float s = 0.f;
#pragma unroll
        for (int c = 0; c < 16; c++) s += p[c * 512];
        wm_s[(i >> 6) * 65 + (i & 63)] = s;
    }
    if (tid < 8) {
        const float* p = g_esp + (size_t)b * 1024 + tid;
        float s = 0.f;
#pragma unroll
        for (int j = 0; j < 128; j++) s += p[j * 8];
        es_s[tid] = s;
    }
    __syncthreads();
    if (tid < 64) {
        int h = tid >> 3, v = tid & 7;
        float s = 0.f;
#pragma unroll 16
        for (int a = 0; a < 64; a++) s = fmaf(wm_s[h * 65 + a], value_w[a * 8 + v], s);
        wa_f[tid] = s / es_s[h];   // k = h*8+v = tid
    }
    __syncthreads();
    // W2 swizzled tf32 image: W2[k][n] = output_w[k][n] * wa[k]
    float* img = g_w2img + (size_t)b * 4096;
#pragma unroll
    for (int j = 0; j < 16; j++) {
        int idx = j * 256 + tid;
        int n = idx >> 6, pc = idx & 63;
        int quad = (pc >> 2) ^ (n & 7);
        int k = quad * 4 + (idx & 3);
        img[idx] = __uint_as_float(f2tf(output_w[k * 64 + n] * wa_f[k]));
    }
}

// ---------------- K3: gate + output (weight images copied in) ----------------
#define SMEM_FLOATS (128 * 64 + 64 * 64 + 128)

__global__ __launch_bounds__(256, 4)
void k_main(const float* __restrict__ q_data,
            const float* __restrict__ gating_b,
            const float* __restrict__ output_b,
            float* __restrict__ out) {
    extern __shared__ float sh[];
    float* qs   = sh;                 // 128 x 64 swizzled: q tile, then gate tile
    float* wb   = sh + 128 * 64;      // 64 x 64 swizzled image
    float* gb_s = wb + 64 * 64;
    float* ob_s = gb_s + 64;

    int b    = blockIdx.y;
    int rt   = blockIdx.x;
    int tid  = threadIdx.x;    // 256
    int warp = tid >> 5;
    int lane = tid & 31;
    int g    = lane >> 2;
    int t    = lane & 3;
    int mw   = warp & 3;
    int hN   = warp >> 2;

    if (tid < 64) {
        gb_s[tid] = gating_b[tid];
        ob_s[tid] = output_b[tid];
    }
    // Gw image -> wb (pure copy, coalesced, conflict-free)
    {
        const float4* src = (const float4*)g_gwimg;
        float4* dst = (float4*)wb;
#pragma unroll
        for (int j = 0; j < 4; j++) dst[j * 256 + tid] = src[j * 256 + tid];
    }
    // q tile -> swizzled tf32 smem
    const float4* qsrc = (const float4*)(q_data + ((size_t)b * NN + (size_t)rt * 128) * QDIM);
#pragma unroll
    for (int it = 0; it < 8; it++) {
        int i = tid + it * 256;
        float4 v = qsrc[i];
        int r = i >> 4, q16 = i & 15;
        float* d = qs + r * 64 + ((q16 ^ (r & 7)) << 2);
        d[0] = __uint_as_float(f2tf(v.x)); d[1] = __uint_as_float(f2tf(v.y));
        d[2] = __uint_as_float(f2tf(v.z)); d[3] = __uint_as_float(f2tf(v.w));
    }
    __syncthreads();

    unsigned qs_base = (unsigned)__cvta_generic_to_shared(qs);
    unsigned wb_base = (unsigned)__cvta_generic_to_shared(wb);
    int mi = lane >> 3;
    unsigned a_rb0 = qs_base + (unsigned)(mw * 32 + (lane & 7) + 8 * (mi & 1)) * 256u;
    unsigned a_rb1 = a_rb0 + 16u * 256u;
    unsigned a_xm  = (unsigned)(lane & 7);
    unsigned a_sel = (unsigned)((lane >> 4) & 1);
    int bm = lane >> 3, brow = lane & 7;
    unsigned b_rb0 = wb_base + (unsigned)(hN * 32 + ((bm >> 1) << 3) + brow) * 256u;
    unsigned b_rb1 = b_rb0 + 16u * 256u;
    unsigned b_xm  = (unsigned)brow;
    unsigned b_sel = (unsigned)(bm & 1);

    float c_[2][4][4];
#pragma unroll
    for (int mt = 0; mt < 2; mt++)
#pragma unroll
        for (int nt = 0; nt < 4; nt++)
#pragma unroll
            for (int e = 0; e < 4; e++) c_[mt][nt][e] = 0.f;

    // ---- mma1: S = Q @ Gw ----
#pragma unroll
    for (int k8 = 0; k8 < 8; k8++) {
        unsigned aq = (((unsigned)(k8 * 2) + a_sel) ^ a_xm) << 4;
        unsigned bq = (((unsigned)(k8 * 2) + b_sel) ^ b_xm) << 4;
        unsigned a0[2], a1[2], a2[2], a3[2];
        ldm_x4(a0[0], a1[0], a2[0], a3[0], a_rb0 + aq);
        ldm_x4(a0[1], a1[1], a2[1], a3[1], a_rb1 + aq);
        unsigned p0b0, p0b1, p0c0, p0c1, p1b0, p1b1, p1c0, p1c1;
        ldm_x4(p0b0, p0b1, p0c0, p0c1, b_rb0 + bq);
        ldm_x4(p1b0, p1b1, p1c0, p1c1, b_rb1 + bq);
        MMA_TF32(c_[0][0], a0[0], a1[0], a2[0], a3[0], p0b0, p0b1);
        MMA_TF32(c_[1][0], a0[1], a1[1], a2[1], a3[1], p0b0, p0b1);
        MMA_TF32(c_[0][1], a0[0], a1[0], a2[0], a3[0], p0c0, p0c1);
        MMA_TF32(c_[1][1], a0[1], a1[1], a2[1], a3[1], p0c0, p0c1);
        MMA_TF32(c_[0][2], a0[0], a1[0], a2[0], a3[0], p1b0, p1b1);
        MMA_TF32(c_[1][2], a0[1], a1[1], a2[1], a3[1], p1b0, p1b1);
        MMA_TF32(c_[0][3], a0[0], a1[0], a2[0], a3[0], p1c0, p1c1);
        MMA_TF32(c_[1][3], a0[1], a1[1], a2[1], a3[1], p1c0, p1c1);
    }

    // ---- sigmoid gate -> qs (swizzled tf32) ----
#pragma unroll
    for (int mt = 0; mt < 2; mt++) {
        int r0 = mw * 32 + mt * 16;
#pragma unroll
        for (int nt = 0; nt < 4; nt++) {
            int col = hN * 32 + nt * 8 + 2 * t;
            float bb0 = gb_s[col], bb1 = gb_s[col + 1];
            float g0 = 1.f / (1.f + __expf(-(c_[mt][nt][0] + bb0)));
            float g1 = 1.f / (1.f + __expf(-(c_[mt][nt][1] + bb1)));
            float g2 = 1.f / (1.f + __expf(-(c_[mt][nt][2] + bb0)));
            float g3 = 1.f / (1.f + __expf(-(c_[mt][nt][3] + bb1)));
            *(float2*)&qs[swz(r0 + g, col)] =
                make_float2(__uint_as_float(f2tf(g0)), __uint_as_float(f2tf(g1)));
            *(float2*)&qs[swz(r0 + 8 + g, col)] =
                make_float2(__uint_as_float(f2tf(g2)), __uint_as_float(f2tf(g3)));
        }
    }
    __syncthreads();
    // ---- W2 image -> wb (pure copy) ----
    {
        const float4* src = (const float4*)(g_w2img + (size_t)b * 4096);
        float4* dst = (float4*)wb;
#pragma unroll
        for (int j = 0; j < 4; j++) dst[j * 256 + tid] = src[j * 256 + tid];
    }
    __syncthreads();

#pragma unroll
    for (int mt = 0; mt < 2; mt++)
#pragma unroll
        for (int nt = 0; nt < 4; nt++)
#pragma unroll
            for (int e = 0; e < 4; e++) c_[mt][nt][e] = 0.f;

    // ---- mma2: out = gate @ W2 ----
#pragma unroll
    for (int k8 = 0; k8 < 8; k8++) {
        unsigned aq = (((unsigned)(k8 * 2) + a_sel) ^ a_xm) << 4;
        unsigned bq = (((unsigned)(k8 * 2) + b_sel) ^ b_xm) << 4;
        unsigned a0[2], a1[2], a2[2], a3[2];
        ldm_x4(a0[0], a1[0], a2[0], a3[0], a_rb0 + aq);
        ldm_x4(a0[1], a1[1], a2[1], a3[1], a_rb1 + aq);
        unsigned p0b0, p0b1, p0c0, p0c1, p1b0, p1b1, p1c0, p1c1;
        ldm_x4(p0b0, p0b1, p0c0, p0c1, b_rb0 + bq);
        ldm_x4(p1b0, p1b1, p1c0, p1c1, b_rb1 + bq);
        MMA_TF32(c_[0][0], a0[0], a1[0], a2[0], a3[0], p0b0, p0b1);
        MMA_TF32(c_[1][0], a0[1], a1[1], a2[1], a3[1], p0b0, p0b1);
        MMA_TF32(c_[0][1], a0[0], a1[0], a2[0], a3[0], p0c0, p0c1);
        MMA_TF32(c_[1][1], a0[1], a1[1], a2[1], a3[1], p0c0, p0c1);
        MMA_TF32(c_[0][2], a0[0], a1[0], a2[0], a3[0], p1b0, p1b1);
        MMA_TF32(c_[1][2], a0[1], a1[1], a2[1], a3[1], p1b0, p1b1);
        MMA_TF32(c_[0][3], a0[0], a1[0], a2[0], a3[0], p1c0, p1c1);
        MMA_TF32(c_[1][3], a0[1], a1[1], a2[1], a3[1], p1c0, p1c1);
    }

    // ---- epilogue ----
    float* outp = out + ((size_t)b * NN + (size_t)rt * 128) * 64;
#pragma unroll
    for (int mt = 0; mt < 2; mt++) {
        int r0 = mw * 32 + mt * 16 + g;
#pragma unroll
        for (int nt = 0; nt < 4; nt++) {
            int col = hN * 32 + nt * 8 + 2 * t;
            float o0 = ob_s[col], o1 = ob_s[col + 1];
            *(float2*)&outp[(size_t)r0 * 64 + col] =
                make_float2(c_[mt][nt][0] + o0, c_[mt][nt][1] + o1);
            *(float2*)&outp[(size_t)(r0 + 8) * 64 + col] =
                make_float2(c_[mt][nt][2] + o0, c_[mt][nt][3] + o1);
        }
    }
}

// ---------------- launch ----------------
extern "C" void kernel_launch(void* const* d_in, const int* in_sizes, int n_in,
                              void* d_out, int out_size) {
    const float* q_data   = (const float*)d_in[0];
    const float* m_data   = (const float*)d_in[1];
    const float* q_mask   = (const float*)d_in[2];
    const float* query_w  = (const float*)d_in[4];
    const float* key_w    = (const float*)d_in[5];
    const float* value_w  = (const float*)d_in[6];
    const float* gating_w = (const float*)d_in[7];
    const float* gating_b = (const float*)d_in[8];
    const float* output_w = (const float*)d_in[9];
    const float* output_b = (const float*)d_in[10];
    float* out = (float*)d_out;

    k_gwprep<<<1, 256>>>(gating_w);
    k_qavg<<<BB * 4, 256>>>(q_data, q_mask);
    k_qk<<<BB, 64>>>(query_w, key_w);
    k_attn2<<<BB * 16, 256>>>(m_data, q_mask);
    k_wafin<<<BB, 256>>>(value_w, output_w);

    int smem = SMEM_FLOATS * 4;
    cudaFuncSetAttribute(k_main, cudaFuncAttributeMaxDynamicSharedMemorySize, smem);
    k_main<<<dim3(NN / 128, BB), 256, smem>>>(q_data, gating_b, output_b, out);
}